// round 14
// baseline (speedup 1.0000x reference)
#include <cuda_runtime.h>
#include <cuda_fp16.h>
#include <stdint.h>

#define BSZ  2
#define CDIM 1024
#define TDIM 2048
#define HN   16
#define DH   64

// ---------------- scratch (static device globals) ----------------
__device__ __half g_Wh [(size_t)4 * CDIM * CDIM];     // [Wq;Wk;Wv;Wp] fp16
__device__ __half g_xTh[(size_t)BSZ * TDIM * CDIM];   // (B, Tc, C) fp16
__device__ __half g_qh [(size_t)BSZ * HN * TDIM * DH]; // (B,H,Tc,D)
__device__ __half g_kh [(size_t)BSZ * HN * TDIM * DH];
__device__ __half g_vh [(size_t)BSZ * CDIM * TDIM];    // (B, C, Tc)
__device__ __half g_aTh[(size_t)BSZ * TDIM * CDIM];    // attn out (B, Tc, C)
__device__ int g_idx[BSZ * TDIM];
__device__ int g_cnt[BSZ];

// ---------------- helpers ----------------
__device__ __forceinline__ uint32_t smem_u32(const void* p) {
    uint32_t a;
    asm("{ .reg .u64 t; cvta.to.shared.u64 t, %1; cvt.u32.u64 %0, t; }" : "=r"(a) : "l"(p));
    return a;
}
__device__ __forceinline__ uint32_t sw128(uint32_t off) { return off ^ ((off >> 3) & 0x70); }

__device__ __forceinline__ void ldsm4(uint32_t* r, uint32_t addr) {
    asm volatile("ldmatrix.sync.aligned.m8n8.x4.shared.b16 {%0,%1,%2,%3}, [%4];"
        : "=r"(r[0]), "=r"(r[1]), "=r"(r[2]), "=r"(r[3]) : "r"(addr));
}
__device__ __forceinline__ void mma16816(float* c, const uint32_t* a, const uint32_t* b) {
    asm volatile("mma.sync.aligned.m16n8k16.row.col.f32.f16.f16.f32 "
        "{%0,%1,%2,%3}, {%4,%5,%6,%7}, {%8,%9}, {%0,%1,%2,%3};"
        : "+f"(c[0]), "+f"(c[1]), "+f"(c[2]), "+f"(c[3])
        : "r"(a[0]), "r"(a[1]), "r"(a[2]), "r"(a[3]), "r"(b[0]), "r"(b[1]));
}
__device__ __forceinline__ uint32_t pack2h(float v0, float v1) {
    return (uint32_t)__half_as_ushort(__float2half(v0)) |
           ((uint32_t)__half_as_ushort(__float2half(v1)) << 16);
}
__device__ __forceinline__ void cpasync16(uint32_t dst, const void* src) {
    asm volatile("cp.async.cg.shared.global [%0], [%1], 16;" :: "r"(dst), "l"(src));
}
#define CP_COMMIT() asm volatile("cp.async.commit_group;" ::: "memory")
#define CP_WAIT0()  asm volatile("cp.async.wait_group 0;" ::: "memory")
#define CP_WAIT1()  asm volatile("cp.async.wait_group 1;" ::: "memory")

// ---------------------------------------------------------------------------
__global__ __launch_bounds__(256)
void compact_kernel(const unsigned* __restrict__ mask, int* __restrict__ idx,
                    int* __restrict__ cnt)
{
    __shared__ int wsum[8];
    __shared__ int wexcl[8];
    const int b = blockIdx.x;
    const unsigned* mb = mask + (size_t)b * TDIM;
    int* ib = idx + (size_t)b * TDIM;
    const int tid  = threadIdx.x;
    const int lane = tid & 31, w = tid >> 5;
    unsigned v[8]; int c = 0;
#pragma unroll
    for (int i = 0; i < 8; ++i) { v[i] = mb[tid * 8 + i]; c += v[i] ? 1 : 0; }
    int inc = c;
#pragma unroll
    for (int off = 1; off < 32; off <<= 1) {
        int n = __shfl_up_sync(0xffffffffu, inc, off);
        if (lane >= off) inc += n;
    }
    if (lane == 31) wsum[w] = inc;
    __syncthreads();
    if (tid == 0) {
        int s = 0;
#pragma unroll
        for (int i = 0; i < 8; ++i) { wexcl[i] = s; s += wsum[i]; }
        cnt[b] = s;
    }
    __syncthreads();
    int p = wexcl[w] + inc - c;
#pragma unroll
    for (int i = 0; i < 8; ++i) if (v[i]) ib[p++] = tid * 8 + i;
}

// ---------------------------------------------------------------------------
// Fused prep: grid sections (split W | zero out | gather-transpose | tail).
// ---------------------------------------------------------------------------
#define PREP_ZERO0    2048
#define PREP_GATH0    2560
#define PREP_TAIL0    6656
#define PREP_BLOCKS   6672

__global__ __launch_bounds__(256)
void prep_kernel(const float* __restrict__ x, const unsigned* __restrict__ mask,
                 const int* __restrict__ idx, const int* __restrict__ cnt,
                 const float* __restrict__ w0, const float* __restrict__ w1,
                 const float* __restrict__ w2, const float* __restrict__ w3,
                 __half* __restrict__ wh, __half* __restrict__ xh,
                 float* __restrict__ out, int writeTail)
{
    const int bx = blockIdx.x;
    const int tid = threadIdx.x;

    if (bx < PREP_ZERO0) {
        const unsigned base = (unsigned)bx * 2048u + (unsigned)tid * 8u;
#pragma unroll
        for (int i = 0; i < 8; i += 4) {
            const unsigned idx4 = base + i;
            const int sel = idx4 >> 20;
            const float* w = (sel == 0) ? w0 : (sel == 1) ? w1 : (sel == 2) ? w2 : w3;
            float4 v = *(const float4*)(w + (idx4 & 0xFFFFFu));
            uint2 o;
            o.x = pack2h(v.x, v.y);
            o.y = pack2h(v.z, v.w);
            *(uint2*)(wh + idx4) = o;
        }
    } else if (bx < PREP_GATH0) {
        float4* p = (float4*)out;
        const unsigned base = (unsigned)(bx - PREP_ZERO0) * 2048u + (unsigned)tid * 8u;
#pragma unroll
        for (int i = 0; i < 8; ++i)
            p[base + i] = make_float4(0.f, 0.f, 0.f, 0.f);
    } else if (bx < PREP_TAIL0) {
        __shared__ float tile[32][33];
        __shared__ int tloc[32];
        const int g = bx - PREP_GATH0;
        const int b = g >> 11;
        const int rem = g & 2047;
        const int cy = rem >> 6;
        const int gx = rem & 63;
        const int n = cnt[b];
        const int i0 = gx * 32;
        if (i0 >= n) return;
        const int c0 = cy * 32;
        const float* s = x + (size_t)b * CDIM * TDIM;
        __half* ph = xh + (size_t)b * TDIM * CDIM;
        const int tx = tid & 31, ty = tid >> 5;
        if (ty == 0) tloc[tx] = (i0 + tx < n) ? idx[b * TDIM + i0 + tx] : -1;
        __syncthreads();
        const int t = tloc[tx];
#pragma unroll
        for (int i = 0; i < 4; ++i)
            tile[ty + i * 8][tx] = (t >= 0) ? s[(size_t)(c0 + ty + i * 8) * TDIM + t] : 0.f;
        __syncthreads();
#pragma unroll
        for (int i = 0; i < 4; ++i) {
            const int irow = i0 + ty + i * 8;
            if (irow < n)
                ph[(size_t)irow * CDIM + c0 + tx] = __float2half(tile[tx][ty + i * 8]);
        }
    } else {
        if (!writeTail) return;
        const int i = (bx - PREP_TAIL0) * 256 + tid;
        float* outTail = out + (size_t)BSZ * CDIM * TDIM;
        outTail[i] = mask[i] ? 1.0f : 0.0f;
    }
}

// ---------------------------------------------------------------------------
// fp16 GEMM, BK=64, 3-stage cp.async pipeline.
// fusedQKV=1: Q/K epilogue staged through smem for coalesced 16B writes.
// ---------------------------------------------------------------------------
extern __shared__ unsigned char dynsm[];

__global__ __launch_bounds__(256, 2)
void mma_gemm(const __half* __restrict__ Ah, const __half* __restrict__ Bh,
              const float* __restrict__ b0, const float* __restrict__ b1,
              const float* __restrict__ b2, float* __restrict__ Cout,
              __half* __restrict__ Qh, __half* __restrict__ Kh, __half* __restrict__ Vh,
              const int* __restrict__ cnt, const int* __restrict__ idx, int fusedQKV)
{
    __shared__ int sidx[128];

    const int b    = blockIdx.z;
    const int nlim = cnt[b];
    const int n0   = blockIdx.x * 128;
    if (n0 >= nlim) return;
    const int m0   = blockIdx.y * 128;
    const int tid  = threadIdx.x;
    const int wid  = tid >> 5;
    const int lane = tid & 31;
    const int wy   = wid & 1;
    const int wx   = wid >> 1;

    const uint32_t smu = smem_u32(dynsm);

    const int r   = tid & 127;
    const int isB = tid >> 7;
    const __half* Bhb = Bh + (size_t)b * TDIM * CDIM;
    const __half* srcP = isB ? (Bhb + (size_t)(n0 + r) * CDIM)
                             : (Ah + (size_t)(m0 + r) * CDIM);
    const uint32_t regOff = (uint32_t)isB * 16384u;
    uint32_t so[8];
#pragma unroll
    for (int i = 0; i < 8; ++i) so[i] = regOff + sw128((uint32_t)r * 128u + i * 16u);

    float acc[4][4][4];
#pragma unroll
    for (int i = 0; i < 4; ++i)
#pragma unroll
        for (int j = 0; j < 4; ++j)
#pragma unroll
            for (int c = 0; c < 4; ++c) acc[i][j][c] = 0.f;

    const uint32_t aRow = (uint32_t)(wy * 64 + (lane & 15));
    const uint32_t aCol = (uint32_t)((lane >> 4) << 4);
    const uint32_t bRow = (uint32_t)(wx * 32 + (lane & 7) + ((lane >> 4) << 3));
    const uint32_t bCol = (uint32_t)(((lane >> 3) & 1) << 4);

    {
#pragma unroll
        for (int i = 0; i < 8; ++i)
            cpasync16(smu + so[i], srcP + i * 8);
        CP_COMMIT();
#pragma unroll
        for (int i = 0; i < 8; ++i)
            cpasync16(smu + 32768u + so[i], srcP + 64 + i * 8);
        CP_COMMIT();
    }

    uint32_t stg = 0;
    uint32_t nst = 2 * 32768u;
    for (int kb = 0; kb < 16; ++kb) {
        if (kb < 15) { CP_WAIT1(); } else { CP_WAIT0(); }
        __syncthreads();
        if (kb + 2 < 16) {
            const int k2 = (kb + 2) * 64;
#pragma unroll
            for (int i = 0; i < 8; ++i)
                cpasync16(smu + nst + so[i], srcP + k2 + i * 8);
            CP_COMMIT();
        }

        const uint32_t smA_u = smu + stg;
        const uint32_t smB_u = smu + stg + 16384;
#pragma unroll
        for (int s = 0; s < 4; ++s) {
            const uint32_t ksA = s * 32;
            uint32_t afr[4][4], bfr[4][2];
#pragma unroll
            for (int mt = 0; mt < 4; ++mt)
                ldsm4(afr[mt], smA_u + sw128((aRow + mt * 16) * 128 + ksA + aCol));
#pragma unroll
            for (int np = 0; np < 2; ++np) {
                uint32_t rr[4];
                ldsm4(rr, smB_u + sw128((bRow + np * 16) * 128 + ksA + bCol));
                bfr[np * 2 + 0][0] = rr[0]; bfr[np * 2 + 0][1] = rr[1];
                bfr[np * 2 + 1][0] = rr[2]; bfr[np * 2 + 1][1] = rr[3];
            }
#pragma unroll
            for (int mt = 0; mt < 4; ++mt)
#pragma unroll
                for (int nt = 0; nt < 4; ++nt)
                    mma16816(acc[mt][nt], afr[mt], bfr[nt]);
        }
        stg = (stg == 2 * 32768u) ? 0u : stg + 32768u;
        nst = (nst == 2 * 32768u) ? 0u : nst + 32768u;
    }

    // ---- epilogue ----
    const int sector = m0 >> 10;
    const int mbase  = m0 & 1023;
    const float* bptr = fusedQKV ? (sector == 0 ? b0 : (sector == 1 ? b1 : b2)) : b0;

    if (!fusedQKV) {
        __syncthreads();
        if (tid < 128) sidx[tid] = (n0 + tid < nlim) ? idx[b * TDIM + n0 + tid] : -1;
        __syncthreads();
    }

    const int qrow = lane >> 2;
    const int qcol = (lane & 3) * 2;

    if (fusedQKV && sector < 2) {
        // staged coalesced epilogue for Q / K
        __half* stage = (__half*)dynsm;   // [128 rows][136 pitch]
        __syncthreads();                  // pipeline smem free
#pragma unroll
        for (int mt = 0; mt < 4; ++mt) {
#pragma unroll
            for (int rh = 0; rh < 2; ++rh) {
                const int rl = wy * 64 + mt * 16 + qrow + rh * 8;
                const float bi = bptr[mbase + rl];
#pragma unroll
                for (int nt = 0; nt < 4; ++nt) {
                    const int cl = wx * 32 + nt * 8 + qcol;
                    *(uint32_t*)&stage[rl * 136 + cl] =
                        pack2h(acc[mt][nt][rh * 2 + 0] + bi,
                               acc[mt][nt][rh * 2 + 1] + bi);
                }
            }
        }
        __syncthreads();
        __half* oh = sector ? Kh : Qh;
#pragma unroll
        for (int w8 = 0; w8 < 8; ++w8) {
            const int w = w8 * 256 + tid;      // 0..2047
            const int t   = w >> 4;
            const int seg = w & 15;
            const int headsel = seg >> 3;
            const int dd0 = (seg & 7) * 8;
            const int rl0 = headsel * 64 + dd0;
            uint4 val;
            __half* tp = (__half*)&val;
#pragma unroll
            for (int i = 0; i < 8; ++i)
                tp[i] = stage[(rl0 + i) * 136 + t];
            const int hh = (mbase >> 6) + headsel;
            const size_t a0 = ((size_t)(b * HN + hh) * TDIM + (n0 + t)) * DH + dd0;
            *(uint4*)(oh + a0) = val;
        }
    } else {
#pragma unroll
        for (int mt = 0; mt < 4; ++mt) {
#pragma unroll
            for (int rh = 0; rh < 2; ++rh) {
                const int rloc = mbase + wy * 64 + mt * 16 + qrow + rh * 8;
                const float bi = bptr[rloc];
#pragma unroll
                for (int nt = 0; nt < 4; ++nt) {
                    const int col = n0 + wx * 32 + nt * 8 + qcol;
                    float v0 = acc[mt][nt][rh * 2 + 0] + bi;
                    float v1 = acc[mt][nt][rh * 2 + 1] + bi;
                    if (!fusedQKV) {
                        float* dst = Cout + (size_t)b * CDIM * TDIM + (size_t)rloc * TDIM;
                        const int t0 = sidx[col - n0 + 0];
                        const int t1 = sidx[col - n0 + 1];
                        if (t0 >= 0) dst[t0] = v0;
                        if (t1 >= 0) dst[t1] = v1;
                    } else {
                        const size_t a0 = ((size_t)b * CDIM + rloc) * TDIM + col;
                        *(uint32_t*)&Vh[a0] = pack2h(v0, v1);
                    }
                }
            }
        }
    }
}

// ---------------------------------------------------------------------------
// fp16 flash attention, double-buffered cp.async K/V, log2-domain softmax
// with branch-skipped rescale.
// ---------------------------------------------------------------------------
__global__ __launch_bounds__(256, 2)
void attn_mma(const __half* __restrict__ Qh, const __half* __restrict__ Kh,
              const __half* __restrict__ Vh, const int* __restrict__ cnt,
              __half* __restrict__ Oh)
{
    __shared__ __align__(1024) unsigned char sm[49152];
    const int b = blockIdx.z, h = blockIdx.y;
    const int kend = cnt[b];
    const int q0 = blockIdx.x * 128;
    if (q0 >= kend) return;
    const int tid = threadIdx.x, wid = tid >> 5, lane = tid & 31;
    const uint32_t smu = smem_u32(sm);

    const __half* Qhb = Qh + ((size_t)(b * HN + h) * TDIM + q0) * DH;
#pragma unroll
    for (int it = 0; it < 4; ++it) {
        const int lin = it * 256 + tid;
        const int row = lin >> 3, qd = lin & 7;
        uint4 a = *(const uint4*)(Qhb + (size_t)row * DH + qd * 8);
        *(uint4*)(sm + 32768 + sw128((uint32_t)row * 128 + qd * 16)) = a;
    }
    __syncthreads();
    uint32_t qfh[4][4];
    {
        const uint32_t aRow = wid * 16 + (lane & 15);
        const uint32_t aColB = (lane >> 4) << 4;
#pragma unroll
        for (int kk = 0; kk < 4; ++kk)
            ldsm4(qfh[kk], smu + 32768 + sw128(aRow * 128 + kk * 32 + aColB));
    }

    float oacc[8][4];
#pragma unroll
    for (int i = 0; i < 8; ++i)
#pragma unroll
        for (int c = 0; c < 4; ++c) oacc[i][c] = 0.f;
    float mrow[2] = {-1e30f, -1e30f}, lrow[2] = {0.f, 0.f};
    const float K2 = 0.18033688f;   // 0.125 * log2(e)
    const uint32_t bRow  = (lane & 7) + ((lane >> 4) << 3);
    const uint32_t bColB = ((lane >> 3) & 1) << 4;
    const int jc = (lane & 3) * 2;

    const __half* Khb = Kh + ((size_t)(b * HN + h) * TDIM) * DH;
    const __half* Vhb = Vh + ((size_t)b * CDIM + h * DH) * TDIM;

    const int l0row = tid >> 3, lqd = tid & 7;
    const int l1row = 32 + l0row;
    const uint32_t soK0 = sw128((uint32_t)l0row * 128 + lqd * 16);
    const uint32_t soK1 = sw128((uint32_t)l1row * 128 + lqd * 16);

    {
        cpasync16(smu + soK0,        Khb + (size_t)l0row * DH + lqd * 8);
        cpasync16(smu + soK1,        Khb + (size_t)l1row * DH + lqd * 8);
        cpasync16(smu + 8192 + soK0, Vhb + (size_t)l0row * TDIM + lqd * 8);
        cpasync16(smu + 8192 + soK1, Vhb + (size_t)l1row * TDIM + lqd * 8);
        CP_COMMIT();
    }

    for (int k0 = 0; k0 < kend; k0 += 64) {
        const uint32_t stg = ((uint32_t)(k0 >> 6) & 1u) * 16384u;
        CP_WAIT0();
        __syncthreads();
        if (k0 + 64 < kend) {
            const uint32_t nst = stg ^ 16384u;
            const int kn = k0 + 64;
            cpasync16(smu + nst + soK0,        Khb + (size_t)(kn + l0row) * DH + lqd * 8);
            cpasync16(smu + nst + soK1,        Khb + (size_t)(kn + l1row) * DH + lqd * 8);
            cpasync16(smu + nst + 8192 + soK0, Vhb + (size_t)l0row * TDIM + kn + lqd * 8);
            cpasync16(smu + nst + 8192 + soK1, Vhb + (size_t)l1row * TDIM + kn + lqd * 8);
            CP_COMMIT();
        }

        float s[8][4];
#pragma unroll
        for (int i = 0; i < 8; ++i)
#pragma unroll
            for (int c = 0; c < 4; ++c) s[i][c] = 0.f;
#pragma unroll
        for (int kk = 0; kk < 4; ++kk) {
            uint32_t bfr[8][2];
#pragma unroll
            for (int np = 0; np < 4; ++np) {
                uint32_t rr[4];
                ldsm4(rr, smu + stg + sw128((np * 16 + bRow) * 128 + kk * 32 + bColB));
                bfr[np * 2 + 0][0] = rr[0]; bfr[np * 2 + 0][1] = rr[1];
                bfr[np * 2 + 1][0] = rr[2]; bfr[np * 2 + 1][1] = rr[3];
            }
#pragma unroll
            for (int nt = 0; nt < 8; ++nt) mma16816(s[nt], qfh[kk], bfr[nt]);
        }

        // ---- log2-domain online softmax, branch-skipped rescale ----
#pragma unroll
        for (int rh = 0; rh < 2; ++rh) {
            float mx = -1e30f;
#pragma unroll
            for (int nt = 0; nt < 8; ++nt) {
                const int jg = k0 + nt * 8 + jc;
                float v0 = (jg     < kend) ? s[nt][rh * 2 + 0] * K2 : -1e30f;
                float v1 = (jg + 1 < kend) ? s[nt][rh * 2 + 1] * K2 : -1e30f;
                s[nt][rh * 2 + 0] = v0; s[nt][rh * 2 + 1] = v1;
                mx = fmaxf(mx, fmaxf(v0, v1));
            }
            mx = fmaxf(mx, __shfl_xor_sync(0xffffffffu, mx, 1));
            mx = fmaxf(mx, __shfl_xor_sync(0xffffffffu, mx, 2));
            if (mx > mrow[rh]) {
                const float fac = exp2f(mrow[rh] - mx);
                mrow[rh] = mx;
                lrow[rh] *= fac;
#pragma unroll
                for (int nt = 0; nt < 8; ++nt) {
                    oacc[nt][rh * 2 + 0] *= fac;
                    oacc[nt][rh * 2 + 1] *= fac;
                }
            }
            const float m2 = mrow[rh];
            float sum = 0.f;
#pragma unroll
            for (int nt = 0; nt < 8; ++nt) {
                float p0 = exp2f(s[nt][rh * 2 + 0] - m2);
                float p1 = exp2f(s[nt][rh * 2 + 1] - m2);
                s[nt][rh * 2 + 0] = p0; s[nt][rh * 2 + 1] = p1;
                sum += p0 + p1;
            }
            sum += __shfl_xor_sync(0xffffffffu, sum, 1);
            sum += __shfl_xor_sync(0xffffffffu, sum, 2);
            lrow[rh] += sum;
        }

        uint32_t ph[4][4];
#pragma unroll
        for (int kk2 = 0; kk2 < 4; ++kk2) {
            const int t0 = 2 * kk2, t1 = 2 * kk2 + 1;
            ph[kk2][0] = pack2h(s[t0][0], s[t0][1]);
            ph[kk2][1] = pack2h(s[t0][2], s[t0][3]);
            ph[kk2][2] = pack2h(s[t1][0], s[t1][1]);
            ph[kk2][3] = pack2h(s[t1][2], s[t1][3]);
        }

#pragma unroll
        for (int kk2 = 0; kk2 < 4; ++kk2) {
            uint32_t vfr[8][2];
#pragma unroll
            for (int np = 0; np < 4; ++np) {
                uint32_t rr[4];
                ldsm4(rr, smu + stg + 8192 + sw128((np * 16 + bRow) * 128 + kk2 * 32 + bColB));
                vfr[np * 2 + 0][0] = rr[0]; vfr[np * 2 + 0][1] = rr[1];
                vfr[np * 2 + 1][0] = rr[2]; vfr[np * 2 + 1][1] = rr[3];
            }
#pragma unroll
            for (int nt = 0; nt < 8; ++nt) mma16816(oacc[nt], ph[kk2], vfr[nt]);
        }
    }

#pragma unroll
    for (int rh = 0; rh < 2; ++rh) {
        const int q = q0 + wid * 16 + (lane >> 2) + rh * 8;
        const float inv = (lrow[rh] > 0.f) ? (1.f / lrow[rh]) : 0.f;
        const size_t base = ((size_t)b * TDIM + q) * CDIM + h * DH;
#pragma unroll
        for (int nt = 0; nt < 8; ++nt) {
            const int d = nt * 8 + jc;
            *(uint32_t*)&Oh[base + d] =
                pack2h(oacc[nt][rh * 2 + 0] * inv, oacc[nt][rh * 2 + 1] * inv);
        }
    }
}

// ---------------------------------------------------------------------------
extern "C" void kernel_launch(void* const* d_in, const int* in_sizes, int n_in,
                              void* d_out, int out_size)
{
    const float*    x    = (const float*)d_in[0];
    const unsigned* mask = (const unsigned*)d_in[1];
    const float*    Wq   = (const float*)d_in[2];
    const float*    bq   = (const float*)d_in[3];
    const float*    Wk   = (const float*)d_in[4];
    const float*    bk   = (const float*)d_in[5];
    const float*    Wv   = (const float*)d_in[6];
    const float*    bv   = (const float*)d_in[7];
    const float*    Wp   = (const float*)d_in[8];
    const float*    bp   = (const float*)d_in[9];
    float* out = (float*)d_out;

    __half *wh, *xh, *ah, *qh, *kh, *vh;
    int *gidx, *gcnt;
    cudaGetSymbolAddress((void**)&wh,   g_Wh);
    cudaGetSymbolAddress((void**)&xh,   g_xTh);
    cudaGetSymbolAddress((void**)&ah,   g_aTh);
    cudaGetSymbolAddress((void**)&qh,   g_qh);
    cudaGetSymbolAddress((void**)&kh,   g_kh);
    cudaGetSymbolAddress((void**)&vh,   g_vh);
    cudaGetSymbolAddress((void**)&gidx, g_idx);
    cudaGetSymbolAddress((void**)&gcnt, g_cnt);

    static int smem_set = 0;
    if (!smem_set) {
        cudaFuncSetAttribute(mma_gemm, cudaFuncAttributeMaxDynamicSharedMemorySize, 98304);
        smem_set = 1;
    }

    const long long nout = (long long)BSZ * CDIM * TDIM;
    const int writeTail = (out_size - (int)nout) >= BSZ * TDIM ? 1 : 0;

    compact_kernel<<<BSZ, 256>>>(mask, gidx, gcnt);

    prep_kernel<<<PREP_BLOCKS, 256>>>(x, mask, gidx, gcnt,
                                      Wq, Wk, Wv, Wp, wh, xh, out, writeTail);

    const size_t WN = (size_t)CDIM * CDIM;
    dim3 gqkv(TDIM / 128, 24, BSZ);
    mma_gemm<<<gqkv, 256, 98304>>>(wh, xh, bq, bk, bv,
                                   nullptr, qh, kh, vh, gcnt, gidx, 1);

    dim3 ga(TDIM / 128, HN, BSZ);
    attn_mma<<<ga, 256>>>(qh, kh, vh, gcnt, ah);

    dim3 gp(TDIM / 128, CDIM / 128, BSZ);
    mma_gemm<<<gp, 256, 98304>>>(wh + 3 * WN, ah, bp, nullptr, nullptr,
                                 out, nullptr, nullptr, nullptr,
                                 gcnt, gidx, 0);
}

// round 15
// speedup vs baseline: 1.0500x; 1.0500x over previous
#include <cuda_runtime.h>
#include <cuda_fp16.h>
#include <stdint.h>

#define BSZ  2
#define CDIM 1024
#define TDIM 2048
#define HN   16
#define DH   64

// ---------------- scratch (static device globals) ----------------
__device__ __half g_Wh [(size_t)4 * CDIM * CDIM];     // [Wq;Wk;Wv;Wp] fp16
__device__ __half g_xTh[(size_t)BSZ * TDIM * CDIM];   // (B, Tc, C) fp16
__device__ __half g_qh [(size_t)BSZ * HN * TDIM * DH]; // (B,H,Tc,D)
__device__ __half g_kh [(size_t)BSZ * HN * TDIM * DH];
__device__ __half g_vh [(size_t)BSZ * CDIM * TDIM];    // (B, C, Tc)
__device__ __half g_aTh[(size_t)BSZ * TDIM * CDIM];    // attn out (B, Tc, C)
__device__ int g_idx[BSZ * TDIM];
__device__ int g_cnt[BSZ];

// ---------------- helpers ----------------
__device__ __forceinline__ uint32_t smem_u32(const void* p) {
    uint32_t a;
    asm("{ .reg .u64 t; cvta.to.shared.u64 t, %1; cvt.u32.u64 %0, t; }" : "=r"(a) : "l"(p));
    return a;
}
__device__ __forceinline__ uint32_t sw128(uint32_t off) { return off ^ ((off >> 3) & 0x70); }

__device__ __forceinline__ void ldsm4(uint32_t* r, uint32_t addr) {
    asm volatile("ldmatrix.sync.aligned.m8n8.x4.shared.b16 {%0,%1,%2,%3}, [%4];"
        : "=r"(r[0]), "=r"(r[1]), "=r"(r[2]), "=r"(r[3]) : "r"(addr));
}
__device__ __forceinline__ void mma16816(float* c, const uint32_t* a, const uint32_t* b) {
    asm volatile("mma.sync.aligned.m16n8k16.row.col.f32.f16.f16.f32 "
        "{%0,%1,%2,%3}, {%4,%5,%6,%7}, {%8,%9}, {%0,%1,%2,%3};"
        : "+f"(c[0]), "+f"(c[1]), "+f"(c[2]), "+f"(c[3])
        : "r"(a[0]), "r"(a[1]), "r"(a[2]), "r"(a[3]), "r"(b[0]), "r"(b[1]));
}
__device__ __forceinline__ uint32_t pack2h(float v0, float v1) {
    return (uint32_t)__half_as_ushort(__float2half(v0)) |
           ((uint32_t)__half_as_ushort(__float2half(v1)) << 16);
}
__device__ __forceinline__ void cpasync16(uint32_t dst, const void* src) {
    asm volatile("cp.async.cg.shared.global [%0], [%1], 16;" :: "r"(dst), "l"(src));
}
#define CP_COMMIT() asm volatile("cp.async.commit_group;" ::: "memory")
#define CP_WAIT0()  asm volatile("cp.async.wait_group 0;" ::: "memory")
#define CP_WAIT1()  asm volatile("cp.async.wait_group 1;" ::: "memory")

// ---------------------------------------------------------------------------
__global__ __launch_bounds__(256)
void compact_kernel(const unsigned* __restrict__ mask, int* __restrict__ idx,
                    int* __restrict__ cnt)
{
    __shared__ int wsum[8];
    __shared__ int wexcl[8];
    const int b = blockIdx.x;
    const unsigned* mb = mask + (size_t)b * TDIM;
    int* ib = idx + (size_t)b * TDIM;
    const int tid  = threadIdx.x;
    const int lane = tid & 31, w = tid >> 5;
    unsigned v[8]; int c = 0;
#pragma unroll
    for (int i = 0; i < 8; ++i) { v[i] = mb[tid * 8 + i]; c += v[i] ? 1 : 0; }
    int inc = c;
#pragma unroll
    for (int off = 1; off < 32; off <<= 1) {
        int n = __shfl_up_sync(0xffffffffu, inc, off);
        if (lane >= off) inc += n;
    }
    if (lane == 31) wsum[w] = inc;
    __syncthreads();
    if (tid == 0) {
        int s = 0;
#pragma unroll
        for (int i = 0; i < 8; ++i) { wexcl[i] = s; s += wsum[i]; }
        cnt[b] = s;
    }
    __syncthreads();
    int p = wexcl[w] + inc - c;
#pragma unroll
    for (int i = 0; i < 8; ++i) if (v[i]) ib[p++] = tid * 8 + i;
}

// ---------------------------------------------------------------------------
// Fused prep: grid sections (split W | zero out | gather-transpose | tail).
// ---------------------------------------------------------------------------
#define PREP_ZERO0    2048
#define PREP_GATH0    2560
#define PREP_TAIL0    6656
#define PREP_BLOCKS   6672

__global__ __launch_bounds__(256)
void prep_kernel(const float* __restrict__ x, const unsigned* __restrict__ mask,
                 const int* __restrict__ idx, const int* __restrict__ cnt,
                 const float* __restrict__ w0, const float* __restrict__ w1,
                 const float* __restrict__ w2, const float* __restrict__ w3,
                 __half* __restrict__ wh, __half* __restrict__ xh,
                 float* __restrict__ out, int writeTail)
{
    const int bx = blockIdx.x;
    const int tid = threadIdx.x;

    if (bx < PREP_ZERO0) {
        const unsigned base = (unsigned)bx * 2048u + (unsigned)tid * 8u;
#pragma unroll
        for (int i = 0; i < 8; i += 4) {
            const unsigned idx4 = base + i;
            const int sel = idx4 >> 20;
            const float* w = (sel == 0) ? w0 : (sel == 1) ? w1 : (sel == 2) ? w2 : w3;
            float4 v = *(const float4*)(w + (idx4 & 0xFFFFFu));
            uint2 o;
            o.x = pack2h(v.x, v.y);
            o.y = pack2h(v.z, v.w);
            *(uint2*)(wh + idx4) = o;
        }
    } else if (bx < PREP_GATH0) {
        float4* p = (float4*)out;
        const unsigned base = (unsigned)(bx - PREP_ZERO0) * 2048u + (unsigned)tid * 8u;
#pragma unroll
        for (int i = 0; i < 8; ++i)
            p[base + i] = make_float4(0.f, 0.f, 0.f, 0.f);
    } else if (bx < PREP_TAIL0) {
        __shared__ float tile[32][33];
        __shared__ int tloc[32];
        const int g = bx - PREP_GATH0;
        const int b = g >> 11;
        const int rem = g & 2047;
        const int cy = rem >> 6;
        const int gx = rem & 63;
        const int n = cnt[b];
        const int i0 = gx * 32;
        if (i0 >= n) return;
        const int c0 = cy * 32;
        const float* s = x + (size_t)b * CDIM * TDIM;
        __half* ph = xh + (size_t)b * TDIM * CDIM;
        const int tx = tid & 31, ty = tid >> 5;
        if (ty == 0) tloc[tx] = (i0 + tx < n) ? idx[b * TDIM + i0 + tx] : -1;
        __syncthreads();
        const int t = tloc[tx];
#pragma unroll
        for (int i = 0; i < 4; ++i)
            tile[ty + i * 8][tx] = (t >= 0) ? s[(size_t)(c0 + ty + i * 8) * TDIM + t] : 0.f;
        __syncthreads();
#pragma unroll
        for (int i = 0; i < 4; ++i) {
            const int irow = i0 + ty + i * 8;
            if (irow < n)
                ph[(size_t)irow * CDIM + c0 + tx] = __float2half(tile[tx][ty + i * 8]);
        }
    } else {
        if (!writeTail) return;
        const int i = (bx - PREP_TAIL0) * 256 + tid;
        float* outTail = out + (size_t)BSZ * CDIM * TDIM;
        outTail[i] = mask[i] ? 1.0f : 0.0f;
    }
}

// ---------------------------------------------------------------------------
// fp16 GEMM, BK=64, 3-stage cp.async pipeline, direct epilogue (R13 form).
// ---------------------------------------------------------------------------
extern __shared__ unsigned char dynsm[];

__global__ __launch_bounds__(256, 2)
void mma_gemm(const __half* __restrict__ Ah, const __half* __restrict__ Bh,
              const float* __restrict__ b0, const float* __restrict__ b1,
              const float* __restrict__ b2, float* __restrict__ Cout,
              __half* __restrict__ Qh, __half* __restrict__ Kh, __half* __restrict__ Vh,
              const int* __restrict__ cnt, const int* __restrict__ idx, int fusedQKV)
{
    __shared__ int sidx[128];

    const int b    = blockIdx.z;
    const int nlim = cnt[b];
    const int n0   = blockIdx.x * 128;
    if (n0 >= nlim) return;
    const int m0   = blockIdx.y * 128;
    const int tid  = threadIdx.x;
    const int wid  = tid >> 5;
    const int lane = tid & 31;
    const int wy   = wid & 1;
    const int wx   = wid >> 1;

    const uint32_t smu = smem_u32(dynsm);

    const int r   = tid & 127;
    const int isB = tid >> 7;
    const __half* Bhb = Bh + (size_t)b * TDIM * CDIM;
    const __half* srcP = isB ? (Bhb + (size_t)(n0 + r) * CDIM)
                             : (Ah + (size_t)(m0 + r) * CDIM);
    const uint32_t regOff = (uint32_t)isB * 16384u;
    uint32_t so[8];
#pragma unroll
    for (int i = 0; i < 8; ++i) so[i] = regOff + sw128((uint32_t)r * 128u + i * 16u);

    float acc[4][4][4];
#pragma unroll
    for (int i = 0; i < 4; ++i)
#pragma unroll
        for (int j = 0; j < 4; ++j)
#pragma unroll
            for (int c = 0; c < 4; ++c) acc[i][j][c] = 0.f;

    const uint32_t aRow = (uint32_t)(wy * 64 + (lane & 15));
    const uint32_t aCol = (uint32_t)((lane >> 4) << 4);
    const uint32_t bRow = (uint32_t)(wx * 32 + (lane & 7) + ((lane >> 4) << 3));
    const uint32_t bCol = (uint32_t)(((lane >> 3) & 1) << 4);

    {
#pragma unroll
        for (int i = 0; i < 8; ++i)
            cpasync16(smu + so[i], srcP + i * 8);
        CP_COMMIT();
#pragma unroll
        for (int i = 0; i < 8; ++i)
            cpasync16(smu + 32768u + so[i], srcP + 64 + i * 8);
        CP_COMMIT();
    }

    uint32_t stg = 0;
    uint32_t nst = 2 * 32768u;
    for (int kb = 0; kb < 16; ++kb) {
        if (kb < 15) { CP_WAIT1(); } else { CP_WAIT0(); }
        __syncthreads();
        if (kb + 2 < 16) {
            const int k2 = (kb + 2) * 64;
#pragma unroll
            for (int i = 0; i < 8; ++i)
                cpasync16(smu + nst + so[i], srcP + k2 + i * 8);
            CP_COMMIT();
        }

        const uint32_t smA_u = smu + stg;
        const uint32_t smB_u = smu + stg + 16384;
#pragma unroll
        for (int s = 0; s < 4; ++s) {
            const uint32_t ksA = s * 32;
            uint32_t afr[4][4], bfr[4][2];
#pragma unroll
            for (int mt = 0; mt < 4; ++mt)
                ldsm4(afr[mt], smA_u + sw128((aRow + mt * 16) * 128 + ksA + aCol));
#pragma unroll
            for (int np = 0; np < 2; ++np) {
                uint32_t rr[4];
                ldsm4(rr, smB_u + sw128((bRow + np * 16) * 128 + ksA + bCol));
                bfr[np * 2 + 0][0] = rr[0]; bfr[np * 2 + 0][1] = rr[1];
                bfr[np * 2 + 1][0] = rr[2]; bfr[np * 2 + 1][1] = rr[3];
            }
#pragma unroll
            for (int mt = 0; mt < 4; ++mt)
#pragma unroll
                for (int nt = 0; nt < 4; ++nt)
                    mma16816(acc[mt][nt], afr[mt], bfr[nt]);
        }
        stg = (stg == 2 * 32768u) ? 0u : stg + 32768u;
        nst = (nst == 2 * 32768u) ? 0u : nst + 32768u;
    }

    // ---- epilogue (direct stores, R13) ----
    const int sector = m0 >> 10;
    const int mbase  = m0 & 1023;
    const float* bptr = fusedQKV ? (sector == 0 ? b0 : (sector == 1 ? b1 : b2)) : b0;

    if (!fusedQKV) {
        __syncthreads();
        if (tid < 128) sidx[tid] = (n0 + tid < nlim) ? idx[b * TDIM + n0 + tid] : -1;
        __syncthreads();
    }

    const int qrow = lane >> 2;
    const int qcol = (lane & 3) * 2;
#pragma unroll
    for (int mt = 0; mt < 4; ++mt) {
#pragma unroll
        for (int rh = 0; rh < 2; ++rh) {
            const int rloc = mbase + wy * 64 + mt * 16 + qrow + rh * 8;
            const float bi = bptr[rloc];
#pragma unroll
            for (int nt = 0; nt < 4; ++nt) {
                const int col = n0 + wx * 32 + nt * 8 + qcol;
                float v0 = acc[mt][nt][rh * 2 + 0] + bi;
                float v1 = acc[mt][nt][rh * 2 + 1] + bi;
                if (!fusedQKV) {
                    float* dst = Cout + (size_t)b * CDIM * TDIM + (size_t)rloc * TDIM;
                    const int t0 = sidx[col - n0 + 0];
                    const int t1 = sidx[col - n0 + 1];
                    if (t0 >= 0) dst[t0] = v0;
                    if (t1 >= 0) dst[t1] = v1;
                } else if (sector < 2) {
                    __half* oh = sector ? Kh : Qh;
                    const int hh = rloc >> 6, dd = rloc & 63;
                    const size_t a0 = ((size_t)(b * HN + hh) * TDIM + col) * DH + dd;
                    oh[a0]      = __float2half(v0);
                    oh[a0 + DH] = __float2half(v1);
                } else {
                    const size_t a0 = ((size_t)b * CDIM + rloc) * TDIM + col;
                    *(uint32_t*)&Vh[a0] = pack2h(v0, v1);
                }
            }
        }
    }
}

// ---------------------------------------------------------------------------
// fp16 flash attention (R14 version: log2-domain softmax, branch-skipped
// rescale, double-buffered cp.async K/V tiles).
// ---------------------------------------------------------------------------
__global__ __launch_bounds__(256, 2)
void attn_mma(const __half* __restrict__ Qh, const __half* __restrict__ Kh,
              const __half* __restrict__ Vh, const int* __restrict__ cnt,
              __half* __restrict__ Oh)
{
    __shared__ __align__(1024) unsigned char sm[49152];
    const int b = blockIdx.z, h = blockIdx.y;
    const int kend = cnt[b];
    const int q0 = blockIdx.x * 128;
    if (q0 >= kend) return;
    const int tid = threadIdx.x, wid = tid >> 5, lane = tid & 31;
    const uint32_t smu = smem_u32(sm);

    const __half* Qhb = Qh + ((size_t)(b * HN + h) * TDIM + q0) * DH;
#pragma unroll
    for (int it = 0; it < 4; ++it) {
        const int lin = it * 256 + tid;
        const int row = lin >> 3, qd = lin & 7;
        uint4 a = *(const uint4*)(Qhb + (size_t)row * DH + qd * 8);
        *(uint4*)(sm + 32768 + sw128((uint32_t)row * 128 + qd * 16)) = a;
    }
    __syncthreads();
    uint32_t qfh[4][4];
    {
        const uint32_t aRow = wid * 16 + (lane & 15);
        const uint32_t aColB = (lane >> 4) << 4;
#pragma unroll
        for (int kk = 0; kk < 4; ++kk)
            ldsm4(qfh[kk], smu + 32768 + sw128(aRow * 128 + kk * 32 + aColB));
    }

    float oacc[8][4];
#pragma unroll
    for (int i = 0; i < 8; ++i)
#pragma unroll
        for (int c = 0; c < 4; ++c) oacc[i][c] = 0.f;
    float mrow[2] = {-1e30f, -1e30f}, lrow[2] = {0.f, 0.f};
    const float K2 = 0.18033688f;   // 0.125 * log2(e)
    const uint32_t bRow  = (lane & 7) + ((lane >> 4) << 3);
    const uint32_t bColB = ((lane >> 3) & 1) << 4;
    const int jc = (lane & 3) * 2;

    const __half* Khb = Kh + ((size_t)(b * HN + h) * TDIM) * DH;
    const __half* Vhb = Vh + ((size_t)b * CDIM + h * DH) * TDIM;

    const int l0row = tid >> 3, lqd = tid & 7;
    const int l1row = 32 + l0row;
    const uint32_t soK0 = sw128((uint32_t)l0row * 128 + lqd * 16);
    const uint32_t soK1 = sw128((uint32_t)l1row * 128 + lqd * 16);

    {
        cpasync16(smu + soK0,        Khb + (size_t)l0row * DH + lqd * 8);
        cpasync16(smu + soK1,        Khb + (size_t)l1row * DH + lqd * 8);
        cpasync16(smu + 8192 + soK0, Vhb + (size_t)l0row * TDIM + lqd * 8);
        cpasync16(smu + 8192 + soK1, Vhb + (size_t)l1row * TDIM + lqd * 8);
        CP_COMMIT();
    }

    for (int k0 = 0; k0 < kend; k0 += 64) {
        const uint32_t stg = ((uint32_t)(k0 >> 6) & 1u) * 16384u;
        CP_WAIT0();
        __syncthreads();
        if (k0 + 64 < kend) {
            const uint32_t nst = stg ^ 16384u;
            const int kn = k0 + 64;
            cpasync16(smu + nst + soK0,        Khb + (size_t)(kn + l0row) * DH + lqd * 8);
            cpasync16(smu + nst + soK1,        Khb + (size_t)(kn + l1row) * DH + lqd * 8);
            cpasync16(smu + nst + 8192 + soK0, Vhb + (size_t)l0row * TDIM + kn + lqd * 8);
            cpasync16(smu + nst + 8192 + soK1, Vhb + (size_t)l1row * TDIM + kn + lqd * 8);
            CP_COMMIT();
        }

        float s[8][4];
#pragma unroll
        for (int i = 0; i < 8; ++i)
#pragma unroll
            for (int c = 0; c < 4; ++c) s[i][c] = 0.f;
#pragma unroll
        for (int kk = 0; kk < 4; ++kk) {
            uint32_t bfr[8][2];
#pragma unroll
            for (int np = 0; np < 4; ++np) {
                uint32_t rr[4];
                ldsm4(rr, smu + stg + sw128((np * 16 + bRow) * 128 + kk * 32 + bColB));
                bfr[np * 2 + 0][0] = rr[0]; bfr[np * 2 + 0][1] = rr[1];
                bfr[np * 2 + 1][0] = rr[2]; bfr[np * 2 + 1][1] = rr[3];
            }
#pragma unroll
            for (int nt = 0; nt < 8; ++nt) mma16816(s[nt], qfh[kk], bfr[nt]);
        }

        // ---- log2-domain online softmax, branch-skipped rescale ----
#pragma unroll
        for (int rh = 0; rh < 2; ++rh) {
            float mx = -1e30f;
#pragma unroll
            for (int nt = 0; nt < 8; ++nt) {
                const int jg = k0 + nt * 8 + jc;
                float v0 = (jg     < kend) ? s[nt][rh * 2 + 0] * K2 : -1e30f;
                float v1 = (jg + 1 < kend) ? s[nt][rh * 2 + 1] * K2 : -1e30f;
                s[nt][rh * 2 + 0] = v0; s[nt][rh * 2 + 1] = v1;
                mx = fmaxf(mx, fmaxf(v0, v1));
            }
            mx = fmaxf(mx, __shfl_xor_sync(0xffffffffu, mx, 1));
            mx = fmaxf(mx, __shfl_xor_sync(0xffffffffu, mx, 2));
            if (mx > mrow[rh]) {
                const float fac = exp2f(mrow[rh] - mx);
                mrow[rh] = mx;
                lrow[rh] *= fac;
#pragma unroll
                for (int nt = 0; nt < 8; ++nt) {
                    oacc[nt][rh * 2 + 0] *= fac;
                    oacc[nt][rh * 2 + 1] *= fac;
                }
            }
            const float m2 = mrow[rh];
            float sum = 0.f;
#pragma unroll
            for (int nt = 0; nt < 8; ++nt) {
                float p0 = exp2f(s[nt][rh * 2 + 0] - m2);
                float p1 = exp2f(s[nt][rh * 2 + 1] - m2);
                s[nt][rh * 2 + 0] = p0; s[nt][rh * 2 + 1] = p1;
                sum += p0 + p1;
            }
            sum += __shfl_xor_sync(0xffffffffu, sum, 1);
            sum += __shfl_xor_sync(0xffffffffu, sum, 2);
            lrow[rh] += sum;
        }

        uint32_t ph[4][4];
#pragma unroll
        for (int kk2 = 0; kk2 < 4; ++kk2) {
            const int t0 = 2 * kk2, t1 = 2 * kk2 + 1;
            ph[kk2][0] = pack2h(s[t0][0], s[t0][1]);
            ph[kk2][1] = pack2h(s[t0][2], s[t0][3]);
            ph[kk2][2] = pack2h(s[t1][0], s[t1][1]);
            ph[kk2][3] = pack2h(s[t1][2], s[t1][3]);
        }

#pragma unroll
        for (int kk2 = 0; kk2 < 4; ++kk2) {
            uint32_t vfr[8][2];
#pragma unroll
            for (int np = 0; np < 4; ++np) {
                uint32_t rr[4];
                ldsm4(rr, smu + stg + 8192 + sw128((np * 16 + bRow) * 128 + kk2 * 32 + bColB));
                vfr[np * 2 + 0][0] = rr[0]; vfr[np * 2 + 0][1] = rr[1];
                vfr[np * 2 + 1][0] = rr[2]; vfr[np * 2 + 1][1] = rr[3];
            }
#pragma unroll
            for (int nt = 0; nt < 8; ++nt) mma16816(oacc[nt], ph[kk2], vfr[nt]);
        }
    }

#pragma unroll
    for (int rh = 0; rh < 2; ++rh) {
        const int q = q0 + wid * 16 + (lane >> 2) + rh * 8;
        const float inv = (lrow[rh] > 0.f) ? (1.f / lrow[rh]) : 0.f;
        const size_t base = ((size_t)b * TDIM + q) * CDIM + h * DH;
#pragma unroll
        for (int nt = 0; nt < 8; ++nt) {
            const int d = nt * 8 + jc;
            *(uint32_t*)&Oh[base + d] =
                pack2h(oacc[nt][rh * 2 + 0] * inv, oacc[nt][rh * 2 + 1] * inv);
        }
    }
}

// ---------------------------------------------------------------------------
extern "C" void kernel_launch(void* const* d_in, const int* in_sizes, int n_in,
                              void* d_out, int out_size)
{
    const float*    x    = (const float*)d_in[0];
    const unsigned* mask = (const unsigned*)d_in[1];
    const float*    Wq   = (const float*)d_in[2];
    const float*    bq   = (const float*)d_in[3];
    const float*    Wk   = (const float*)d_in[4];
    const float*    bk   = (const float*)d_in[5];
    const float*    Wv   = (const float*)d_in[6];
    const float*    bv   = (const float*)d_in[7];
    const float*    Wp   = (const float*)d_in[8];
    const float*    bp   = (const float*)d_in[9];
    float* out = (float*)d_out;

    __half *wh, *xh, *ah, *qh, *kh, *vh;
    int *gidx, *gcnt;
    cudaGetSymbolAddress((void**)&wh,   g_Wh);
    cudaGetSymbolAddress((void**)&xh,   g_xTh);
    cudaGetSymbolAddress((void**)&ah,   g_aTh);
    cudaGetSymbolAddress((void**)&qh,   g_qh);
    cudaGetSymbolAddress((void**)&kh,   g_kh);
    cudaGetSymbolAddress((void**)&vh,   g_vh);
    cudaGetSymbolAddress((void**)&gidx, g_idx);
    cudaGetSymbolAddress((void**)&gcnt, g_cnt);

    static int smem_set = 0;
    if (!smem_set) {
        cudaFuncSetAttribute(mma_gemm, cudaFuncAttributeMaxDynamicSharedMemorySize, 98304);
        smem_set = 1;
    }

    const long long nout = (long long)BSZ * CDIM * TDIM;
    const int writeTail = (out_size - (int)nout) >= BSZ * TDIM ? 1 : 0;

    compact_kernel<<<BSZ, 256>>>(mask, gidx, gcnt);

    prep_kernel<<<PREP_BLOCKS, 256>>>(x, mask, gidx, gcnt,
                                      Wq, Wk, Wv, Wp, wh, xh, out, writeTail);

    const size_t WN = (size_t)CDIM * CDIM;
    dim3 gqkv(TDIM / 128, 24, BSZ);
    mma_gemm<<<gqkv, 256, 98304>>>(wh, xh, bq, bk, bv,
                                   nullptr, qh, kh, vh, gcnt, gidx, 1);

    dim3 ga(TDIM / 128, HN, BSZ);
    attn_mma<<<ga, 256>>>(qh, kh, vh, gcnt, ah);

    dim3 gp(TDIM / 128, CDIM / 128, BSZ);
    mma_gemm<<<gp, 256, 98304>>>(wh + 3 * WN, ah, bp, nullptr, nullptr,
                                 out, nullptr, nullptr, nullptr,
                                 gcnt, gidx, 0);
}

// round 16
// speedup vs baseline: 1.0539x; 1.0037x over previous
#include <cuda_runtime.h>
#include <cuda_fp16.h>
#include <stdint.h>

#define BSZ  2
#define CDIM 1024
#define TDIM 2048
#define HN   16
#define DH   64

// ---------------- scratch (static device globals) ----------------
__device__ __half g_Wh [(size_t)4 * CDIM * CDIM];     // [Wq;Wk;Wv;Wp] fp16
__device__ __half g_xTh[(size_t)BSZ * TDIM * CDIM];   // (B, Tc, C) fp16
__device__ __half g_qh [(size_t)BSZ * HN * TDIM * DH]; // (B,H,Tc,D)
__device__ __half g_kh [(size_t)BSZ * HN * TDIM * DH];
__device__ __half g_vh [(size_t)BSZ * CDIM * TDIM];    // (B, C, Tc)
__device__ __half g_aTh[(size_t)BSZ * TDIM * CDIM];    // attn out (B, Tc, C)
__device__ int g_idx[BSZ * TDIM];
__device__ int g_cnt[BSZ];

// ---------------- helpers ----------------
__device__ __forceinline__ uint32_t smem_u32(const void* p) {
    uint32_t a;
    asm("{ .reg .u64 t; cvta.to.shared.u64 t, %1; cvt.u32.u64 %0, t; }" : "=r"(a) : "l"(p));
    return a;
}
__device__ __forceinline__ uint32_t sw128(uint32_t off) { return off ^ ((off >> 3) & 0x70); }

__device__ __forceinline__ void ldsm4(uint32_t* r, uint32_t addr) {
    asm volatile("ldmatrix.sync.aligned.m8n8.x4.shared.b16 {%0,%1,%2,%3}, [%4];"
        : "=r"(r[0]), "=r"(r[1]), "=r"(r[2]), "=r"(r[3]) : "r"(addr));
}
__device__ __forceinline__ void mma16816(float* c, const uint32_t* a, const uint32_t* b) {
    asm volatile("mma.sync.aligned.m16n8k16.row.col.f32.f16.f16.f32 "
        "{%0,%1,%2,%3}, {%4,%5,%6,%7}, {%8,%9}, {%0,%1,%2,%3};"
        : "+f"(c[0]), "+f"(c[1]), "+f"(c[2]), "+f"(c[3])
        : "r"(a[0]), "r"(a[1]), "r"(a[2]), "r"(a[3]), "r"(b[0]), "r"(b[1]));
}
__device__ __forceinline__ uint32_t pack2h(float v0, float v1) {
    return (uint32_t)__half_as_ushort(__float2half(v0)) |
           ((uint32_t)__half_as_ushort(__float2half(v1)) << 16);
}
__device__ __forceinline__ void cpasync16(uint32_t dst, const void* src) {
    asm volatile("cp.async.cg.shared.global [%0], [%1], 16;" :: "r"(dst), "l"(src));
}
#define CP_COMMIT() asm volatile("cp.async.commit_group;" ::: "memory")
#define CP_WAIT0()  asm volatile("cp.async.wait_group 0;" ::: "memory")
#define CP_WAIT1()  asm volatile("cp.async.wait_group 1;" ::: "memory")

// ---------------------------------------------------------------------------
__global__ __launch_bounds__(256)
void compact_kernel(const unsigned* __restrict__ mask, int* __restrict__ idx,
                    int* __restrict__ cnt)
{
    __shared__ int wsum[8];
    __shared__ int wexcl[8];
    const int b = blockIdx.x;
    const unsigned* mb = mask + (size_t)b * TDIM;
    int* ib = idx + (size_t)b * TDIM;
    const int tid  = threadIdx.x;
    const int lane = tid & 31, w = tid >> 5;
    unsigned v[8]; int c = 0;
#pragma unroll
    for (int i = 0; i < 8; ++i) { v[i] = mb[tid * 8 + i]; c += v[i] ? 1 : 0; }
    int inc = c;
#pragma unroll
    for (int off = 1; off < 32; off <<= 1) {
        int n = __shfl_up_sync(0xffffffffu, inc, off);
        if (lane >= off) inc += n;
    }
    if (lane == 31) wsum[w] = inc;
    __syncthreads();
    if (tid == 0) {
        int s = 0;
#pragma unroll
        for (int i = 0; i < 8; ++i) { wexcl[i] = s; s += wsum[i]; }
        cnt[b] = s;
    }
    __syncthreads();
    int p = wexcl[w] + inc - c;
#pragma unroll
    for (int i = 0; i < 8; ++i) if (v[i]) ib[p++] = tid * 8 + i;
}

// ---------------------------------------------------------------------------
// Fused prep: grid sections (split W | zero out | gather-transpose | tail).
// ---------------------------------------------------------------------------
#define PREP_ZERO0    2048
#define PREP_GATH0    2560
#define PREP_TAIL0    6656
#define PREP_BLOCKS   6672

__global__ __launch_bounds__(256)
void prep_kernel(const float* __restrict__ x, const unsigned* __restrict__ mask,
                 const int* __restrict__ idx, const int* __restrict__ cnt,
                 const float* __restrict__ w0, const float* __restrict__ w1,
                 const float* __restrict__ w2, const float* __restrict__ w3,
                 __half* __restrict__ wh, __half* __restrict__ xh,
                 float* __restrict__ out, int writeTail)
{
    const int bx = blockIdx.x;
    const int tid = threadIdx.x;

    if (bx < PREP_ZERO0) {
        const unsigned base = (unsigned)bx * 2048u + (unsigned)tid * 8u;
#pragma unroll
        for (int i = 0; i < 8; i += 4) {
            const unsigned idx4 = base + i;
            const int sel = idx4 >> 20;
            const float* w = (sel == 0) ? w0 : (sel == 1) ? w1 : (sel == 2) ? w2 : w3;
            float4 v = *(const float4*)(w + (idx4 & 0xFFFFFu));
            uint2 o;
            o.x = pack2h(v.x, v.y);
            o.y = pack2h(v.z, v.w);
            *(uint2*)(wh + idx4) = o;
        }
    } else if (bx < PREP_GATH0) {
        float4* p = (float4*)out;
        const unsigned base = (unsigned)(bx - PREP_ZERO0) * 2048u + (unsigned)tid * 8u;
#pragma unroll
        for (int i = 0; i < 8; ++i)
            p[base + i] = make_float4(0.f, 0.f, 0.f, 0.f);
    } else if (bx < PREP_TAIL0) {
        __shared__ float tile[32][33];
        __shared__ int tloc[32];
        const int g = bx - PREP_GATH0;
        const int b = g >> 11;
        const int rem = g & 2047;
        const int cy = rem >> 6;
        const int gx = rem & 63;
        const int n = cnt[b];
        const int i0 = gx * 32;
        if (i0 >= n) return;
        const int c0 = cy * 32;
        const float* s = x + (size_t)b * CDIM * TDIM;
        __half* ph = xh + (size_t)b * TDIM * CDIM;
        const int tx = tid & 31, ty = tid >> 5;
        if (ty == 0) tloc[tx] = (i0 + tx < n) ? idx[b * TDIM + i0 + tx] : -1;
        __syncthreads();
        const int t = tloc[tx];
#pragma unroll
        for (int i = 0; i < 4; ++i)
            tile[ty + i * 8][tx] = (t >= 0) ? s[(size_t)(c0 + ty + i * 8) * TDIM + t] : 0.f;
        __syncthreads();
#pragma unroll
        for (int i = 0; i < 4; ++i) {
            const int irow = i0 + ty + i * 8;
            if (irow < n)
                ph[(size_t)irow * CDIM + c0 + tx] = __float2half(tile[tx][ty + i * 8]);
        }
    } else {
        if (!writeTail) return;
        const int i = (bx - PREP_TAIL0) * 256 + tid;
        float* outTail = out + (size_t)BSZ * CDIM * TDIM;
        outTail[i] = mask[i] ? 1.0f : 0.0f;
    }
}

// ---------------------------------------------------------------------------
// fp16 GEMM, BK=64, 3-stage cp.async pipeline, direct epilogue.
// ---------------------------------------------------------------------------
extern __shared__ unsigned char dynsm[];

__global__ __launch_bounds__(256, 2)
void mma_gemm(const __half* __restrict__ Ah, const __half* __restrict__ Bh,
              const float* __restrict__ b0, const float* __restrict__ b1,
              const float* __restrict__ b2, float* __restrict__ Cout,
              __half* __restrict__ Qh, __half* __restrict__ Kh, __half* __restrict__ Vh,
              const int* __restrict__ cnt, const int* __restrict__ idx, int fusedQKV)
{
    __shared__ int sidx[128];

    const int b    = blockIdx.z;
    const int nlim = cnt[b];
    const int n0   = blockIdx.x * 128;
    if (n0 >= nlim) return;
    const int m0   = blockIdx.y * 128;
    const int tid  = threadIdx.x;
    const int wid  = tid >> 5;
    const int lane = tid & 31;
    const int wy   = wid & 1;
    const int wx   = wid >> 1;

    const uint32_t smu = smem_u32(dynsm);

    const int r   = tid & 127;
    const int isB = tid >> 7;
    const __half* Bhb = Bh + (size_t)b * TDIM * CDIM;
    const __half* srcP = isB ? (Bhb + (size_t)(n0 + r) * CDIM)
                             : (Ah + (size_t)(m0 + r) * CDIM);
    const uint32_t regOff = (uint32_t)isB * 16384u;
    uint32_t so[8];
#pragma unroll
    for (int i = 0; i < 8; ++i) so[i] = regOff + sw128((uint32_t)r * 128u + i * 16u);

    float acc[4][4][4];
#pragma unroll
    for (int i = 0; i < 4; ++i)
#pragma unroll
        for (int j = 0; j < 4; ++j)
#pragma unroll
            for (int c = 0; c < 4; ++c) acc[i][j][c] = 0.f;

    const uint32_t aRow = (uint32_t)(wy * 64 + (lane & 15));
    const uint32_t aCol = (uint32_t)((lane >> 4) << 4);
    const uint32_t bRow = (uint32_t)(wx * 32 + (lane & 7) + ((lane >> 4) << 3));
    const uint32_t bCol = (uint32_t)(((lane >> 3) & 1) << 4);

    {
#pragma unroll
        for (int i = 0; i < 8; ++i)
            cpasync16(smu + so[i], srcP + i * 8);
        CP_COMMIT();
#pragma unroll
        for (int i = 0; i < 8; ++i)
            cpasync16(smu + 32768u + so[i], srcP + 64 + i * 8);
        CP_COMMIT();
    }

    uint32_t stg = 0;
    uint32_t nst = 2 * 32768u;
    for (int kb = 0; kb < 16; ++kb) {
        if (kb < 15) { CP_WAIT1(); } else { CP_WAIT0(); }
        __syncthreads();
        if (kb + 2 < 16) {
            const int k2 = (kb + 2) * 64;
#pragma unroll
            for (int i = 0; i < 8; ++i)
                cpasync16(smu + nst + so[i], srcP + k2 + i * 8);
            CP_COMMIT();
        }

        const uint32_t smA_u = smu + stg;
        const uint32_t smB_u = smu + stg + 16384;
#pragma unroll
        for (int s = 0; s < 4; ++s) {
            const uint32_t ksA = s * 32;
            uint32_t afr[4][4], bfr[4][2];
#pragma unroll
            for (int mt = 0; mt < 4; ++mt)
                ldsm4(afr[mt], smA_u + sw128((aRow + mt * 16) * 128 + ksA + aCol));
#pragma unroll
            for (int np = 0; np < 2; ++np) {
                uint32_t rr[4];
                ldsm4(rr, smB_u + sw128((bRow + np * 16) * 128 + ksA + bCol));
                bfr[np * 2 + 0][0] = rr[0]; bfr[np * 2 + 0][1] = rr[1];
                bfr[np * 2 + 1][0] = rr[2]; bfr[np * 2 + 1][1] = rr[3];
            }
#pragma unroll
            for (int mt = 0; mt < 4; ++mt)
#pragma unroll
                for (int nt = 0; nt < 4; ++nt)
                    mma16816(acc[mt][nt], afr[mt], bfr[nt]);
        }
        stg = (stg == 2 * 32768u) ? 0u : stg + 32768u;
        nst = (nst == 2 * 32768u) ? 0u : nst + 32768u;
    }

    // ---- epilogue (direct stores) ----
    const int sector = m0 >> 10;
    const int mbase  = m0 & 1023;
    const float* bptr = fusedQKV ? (sector == 0 ? b0 : (sector == 1 ? b1 : b2)) : b0;

    if (!fusedQKV) {
        __syncthreads();
        if (tid < 128) sidx[tid] = (n0 + tid < nlim) ? idx[b * TDIM + n0 + tid] : -1;
        __syncthreads();
    }

    const int qrow = lane >> 2;
    const int qcol = (lane & 3) * 2;
#pragma unroll
    for (int mt = 0; mt < 4; ++mt) {
#pragma unroll
        for (int rh = 0; rh < 2; ++rh) {
            const int rloc = mbase + wy * 64 + mt * 16 + qrow + rh * 8;
            const float bi = bptr[rloc];
#pragma unroll
            for (int nt = 0; nt < 4; ++nt) {
                const int col = n0 + wx * 32 + nt * 8 + qcol;
                float v0 = acc[mt][nt][rh * 2 + 0] + bi;
                float v1 = acc[mt][nt][rh * 2 + 1] + bi;
                if (!fusedQKV) {
                    float* dst = Cout + (size_t)b * CDIM * TDIM + (size_t)rloc * TDIM;
                    const int t0 = sidx[col - n0 + 0];
                    const int t1 = sidx[col - n0 + 1];
                    if (t0 >= 0) dst[t0] = v0;
                    if (t1 >= 0) dst[t1] = v1;
                } else if (sector < 2) {
                    __half* oh = sector ? Kh : Qh;
                    const int hh = rloc >> 6, dd = rloc & 63;
                    const size_t a0 = ((size_t)(b * HN + hh) * TDIM + col) * DH + dd;
                    oh[a0]      = __float2half(v0);
                    oh[a0 + DH] = __float2half(v1);
                } else {
                    const size_t a0 = ((size_t)b * CDIM + rloc) * TDIM + col;
                    *(uint32_t*)&Vh[a0] = pack2h(v0, v1);
                }
            }
        }
    }
}

// ---------------------------------------------------------------------------
// fp16 flash attention: log2-domain softmax, branch-skipped rescale,
// double-buffered cp.async K/V, boundary checks peeled to the last tile.
// ---------------------------------------------------------------------------
__global__ __launch_bounds__(256, 2)
void attn_mma(const __half* __restrict__ Qh, const __half* __restrict__ Kh,
              const __half* __restrict__ Vh, const int* __restrict__ cnt,
              __half* __restrict__ Oh)
{
    __shared__ __align__(1024) unsigned char sm[49152];
    const int b = blockIdx.z, h = blockIdx.y;
    const int kend = cnt[b];
    const int q0 = blockIdx.x * 128;
    if (q0 >= kend) return;
    const int tid = threadIdx.x, wid = tid >> 5, lane = tid & 31;
    const uint32_t smu = smem_u32(sm);

    const __half* Qhb = Qh + ((size_t)(b * HN + h) * TDIM + q0) * DH;
#pragma unroll
    for (int it = 0; it < 4; ++it) {
        const int lin = it * 256 + tid;
        const int row = lin >> 3, qd = lin & 7;
        uint4 a = *(const uint4*)(Qhb + (size_t)row * DH + qd * 8);
        *(uint4*)(sm + 32768 + sw128((uint32_t)row * 128 + qd * 16)) = a;
    }
    __syncthreads();
    uint32_t qfh[4][4];
    {
        const uint32_t aRow = wid * 16 + (lane & 15);
        const uint32_t aColB = (lane >> 4) << 4;
#pragma unroll
        for (int kk = 0; kk < 4; ++kk)
            ldsm4(qfh[kk], smu + 32768 + sw128(aRow * 128 + kk * 32 + aColB));
    }

    float oacc[8][4];
#pragma unroll
    for (int i = 0; i < 8; ++i)
#pragma unroll
        for (int c = 0; c < 4; ++c) oacc[i][c] = 0.f;
    float mrow[2] = {-1e30f, -1e30f}, lrow[2] = {0.f, 0.f};
    const float K2 = 0.18033688f;   // 0.125 * log2(e)
    const uint32_t bRow  = (lane & 7) + ((lane >> 4) << 3);
    const uint32_t bColB = ((lane >> 3) & 1) << 4;
    const int jc = (lane & 3) * 2;

    const __half* Khb = Kh + ((size_t)(b * HN + h) * TDIM) * DH;
    const __half* Vhb = Vh + ((size_t)b * CDIM + h * DH) * TDIM;

    const int l0row = tid >> 3, lqd = tid & 7;
    const int l1row = 32 + l0row;
    const uint32_t soK0 = sw128((uint32_t)l0row * 128 + lqd * 16);
    const uint32_t soK1 = sw128((uint32_t)l1row * 128 + lqd * 16);

    {
        cpasync16(smu + soK0,        Khb + (size_t)l0row * DH + lqd * 8);
        cpasync16(smu + soK1,        Khb + (size_t)l1row * DH + lqd * 8);
        cpasync16(smu + 8192 + soK0, Vhb + (size_t)l0row * TDIM + lqd * 8);
        cpasync16(smu + 8192 + soK1, Vhb + (size_t)l1row * TDIM + lqd * 8);
        CP_COMMIT();
    }

    for (int k0 = 0; k0 < kend; k0 += 64) {
        const uint32_t stg = ((uint32_t)(k0 >> 6) & 1u) * 16384u;
        CP_WAIT0();
        __syncthreads();
        if (k0 + 64 < kend) {
            const uint32_t nst = stg ^ 16384u;
            const int kn = k0 + 64;
            cpasync16(smu + nst + soK0,        Khb + (size_t)(kn + l0row) * DH + lqd * 8);
            cpasync16(smu + nst + soK1,        Khb + (size_t)(kn + l1row) * DH + lqd * 8);
            cpasync16(smu + nst + 8192 + soK0, Vhb + (size_t)l0row * TDIM + kn + lqd * 8);
            cpasync16(smu + nst + 8192 + soK1, Vhb + (size_t)l1row * TDIM + kn + lqd * 8);
            CP_COMMIT();
        }

        float s[8][4];
#pragma unroll
        for (int i = 0; i < 8; ++i)
#pragma unroll
            for (int c = 0; c < 4; ++c) s[i][c] = 0.f;
#pragma unroll
        for (int kk = 0; kk < 4; ++kk) {
            uint32_t bfr[8][2];
#pragma unroll
            for (int np = 0; np < 4; ++np) {
                uint32_t rr[4];
                ldsm4(rr, smu + stg + sw128((np * 16 + bRow) * 128 + kk * 32 + bColB));
                bfr[np * 2 + 0][0] = rr[0]; bfr[np * 2 + 0][1] = rr[1];
                bfr[np * 2 + 1][0] = rr[2]; bfr[np * 2 + 1][1] = rr[3];
            }
#pragma unroll
            for (int nt = 0; nt < 8; ++nt) mma16816(s[nt], qfh[kk], bfr[nt]);
        }

        // ---- log2-domain online softmax; boundary checks only in edge tile ----
        const bool edge = (k0 + 64) > kend;
#pragma unroll
        for (int rh = 0; rh < 2; ++rh) {
            float mx = -1e30f;
            if (!edge) {
#pragma unroll
                for (int nt = 0; nt < 8; ++nt) {
                    float v0 = s[nt][rh * 2 + 0] * K2;
                    float v1 = s[nt][rh * 2 + 1] * K2;
                    s[nt][rh * 2 + 0] = v0; s[nt][rh * 2 + 1] = v1;
                    mx = fmaxf(mx, fmaxf(v0, v1));
                }
            } else {
#pragma unroll
                for (int nt = 0; nt < 8; ++nt) {
                    const int jg = k0 + nt * 8 + jc;
                    float v0 = (jg     < kend) ? s[nt][rh * 2 + 0] * K2 : -1e30f;
                    float v1 = (jg + 1 < kend) ? s[nt][rh * 2 + 1] * K2 : -1e30f;
                    s[nt][rh * 2 + 0] = v0; s[nt][rh * 2 + 1] = v1;
                    mx = fmaxf(mx, fmaxf(v0, v1));
                }
            }
            mx = fmaxf(mx, __shfl_xor_sync(0xffffffffu, mx, 1));
            mx = fmaxf(mx, __shfl_xor_sync(0xffffffffu, mx, 2));
            if (mx > mrow[rh]) {
                const float fac = exp2f(mrow[rh] - mx);
                mrow[rh] = mx;
                lrow[rh] *= fac;
#pragma unroll
                for (int nt = 0; nt < 8; ++nt) {
                    oacc[nt][rh * 2 + 0] *= fac;
                    oacc[nt][rh * 2 + 1] *= fac;
                }
            }
            const float m2 = mrow[rh];
            float sum = 0.f;
#pragma unroll
            for (int nt = 0; nt < 8; ++nt) {
                float p0 = exp2f(s[nt][rh * 2 + 0] - m2);
                float p1 = exp2f(s[nt][rh * 2 + 1] - m2);
                s[nt][rh * 2 + 0] = p0; s[nt][rh * 2 + 1] = p1;
                sum += p0 + p1;
            }
            sum += __shfl_xor_sync(0xffffffffu, sum, 1);
            sum += __shfl_xor_sync(0xffffffffu, sum, 2);
            lrow[rh] += sum;
        }

        uint32_t ph[4][4];
#pragma unroll
        for (int kk2 = 0; kk2 < 4; ++kk2) {
            const int t0 = 2 * kk2, t1 = 2 * kk2 + 1;
            ph[kk2][0] = pack2h(s[t0][0], s[t0][1]);
            ph[kk2][1] = pack2h(s[t0][2], s[t0][3]);
            ph[kk2][2] = pack2h(s[t1][0], s[t1][1]);
            ph[kk2][3] = pack2h(s[t1][2], s[t1][3]);
        }

#pragma unroll
        for (int kk2 = 0; kk2 < 4; ++kk2) {
            uint32_t vfr[8][2];
#pragma unroll
            for (int np = 0; np < 4; ++np) {
                uint32_t rr[4];
                ldsm4(rr, smu + stg + 8192 + sw128((np * 16 + bRow) * 128 + kk2 * 32 + bColB));
                vfr[np * 2 + 0][0] = rr[0]; vfr[np * 2 + 0][1] = rr[1];
                vfr[np * 2 + 1][0] = rr[2]; vfr[np * 2 + 1][1] = rr[3];
            }
#pragma unroll
            for (int nt = 0; nt < 8; ++nt) mma16816(oacc[nt], ph[kk2], vfr[nt]);
        }
    }

#pragma unroll
    for (int rh = 0; rh < 2; ++rh) {
        const int q = q0 + wid * 16 + (lane >> 2) + rh * 8;
        const float inv = (lrow[rh] > 0.f) ? (1.f / lrow[rh]) : 0.f;
        const size_t base = ((size_t)b * TDIM + q) * CDIM + h * DH;
#pragma unroll
        for (int nt = 0; nt < 8; ++nt) {
            const int d = nt * 8 + jc;
            *(uint32_t*)&Oh[base + d] =
                pack2h(oacc[nt][rh * 2 + 0] * inv, oacc[nt][rh * 2 + 1] * inv);
        }
    }
}

// ---------------------------------------------------------------------------
extern "C" void kernel_launch(void* const* d_in, const int* in_sizes, int n_in,
                              void* d_out, int out_size)
{
    const float*    x    = (const float*)d_in[0];
    const unsigned* mask = (const unsigned*)d_in[1];
    const float*    Wq   = (const float*)d_in[2];
    const float*    bq   = (const float*)d_in[3];
    const float*    Wk   = (const float*)d_in[4];
    const float*    bk   = (const float*)d_in[5];
    const float*    Wv   = (const float*)d_in[6];
    const float*    bv   = (const float*)d_in[7];
    const float*    Wp   = (const float*)d_in[8];
    const float*    bp   = (const float*)d_in[9];
    float* out = (float*)d_out;

    __half *wh, *xh, *ah, *qh, *kh, *vh;
    int *gidx, *gcnt;
    cudaGetSymbolAddress((void**)&wh,   g_Wh);
    cudaGetSymbolAddress((void**)&xh,   g_xTh);
    cudaGetSymbolAddress((void**)&ah,   g_aTh);
    cudaGetSymbolAddress((void**)&qh,   g_qh);
    cudaGetSymbolAddress((void**)&kh,   g_kh);
    cudaGetSymbolAddress((void**)&vh,   g_vh);
    cudaGetSymbolAddress((void**)&gidx, g_idx);
    cudaGetSymbolAddress((void**)&gcnt, g_cnt);

    static int smem_set = 0;
    if (!smem_set) {
        cudaFuncSetAttribute(mma_gemm, cudaFuncAttributeMaxDynamicSharedMemorySize, 98304);
        smem_set = 1;
    }

    const long long nout = (long long)BSZ * CDIM * TDIM;
    const int writeTail = (out_size - (int)nout) >= BSZ * TDIM ? 1 : 0;

    compact_kernel<<<BSZ, 256>>>(mask, gidx, gcnt);

    prep_kernel<<<PREP_BLOCKS, 256>>>(x, mask, gidx, gcnt,
                                      Wq, Wk, Wv, Wp, wh, xh, out, writeTail);

    const size_t WN = (size_t)CDIM * CDIM;
    dim3 gqkv(TDIM / 128, 24, BSZ);
    mma_gemm<<<gqkv, 256, 98304>>>(wh, xh, bq, bk, bv,
                                   nullptr, qh, kh, vh, gcnt, gidx, 1);

    dim3 ga(TDIM / 128, HN, BSZ);
    attn_mma<<<ga, 256>>>(qh, kh, vh, gcnt, ah);

    dim3 gp(TDIM / 128, CDIM / 128, BSZ);
    mma_gemm<<<gp, 256, 98304>>>(wh + 3 * WN, ah, bp, nullptr, nullptr,
                                 out, nullptr, nullptr, nullptr,
                                 gcnt, gidx, 0);
}

// round 17
// speedup vs baseline: 1.0638x; 1.0094x over previous
#include <cuda_runtime.h>
#include <cuda_fp16.h>
#include <stdint.h>

#define BSZ  2
#define CDIM 1024
#define TDIM 2048
#define HN   16
#define DH   64

// ---------------- scratch (static device globals) ----------------
__device__ __half g_Wh [(size_t)4 * CDIM * CDIM];     // [Wq;Wk;Wv;Wp] fp16
__device__ __half g_xTh[(size_t)BSZ * TDIM * CDIM];   // (B, Tc, C) fp16
__device__ __half g_qh [(size_t)BSZ * HN * TDIM * DH]; // (B,H,Tc,D)
__device__ __half g_kh [(size_t)BSZ * HN * TDIM * DH];
__device__ __half g_vh [(size_t)BSZ * CDIM * TDIM];    // (B, C, Tc)
__device__ __half g_aTh[(size_t)BSZ * TDIM * CDIM];    // attn out (B, Tc, C)
__device__ int g_idx[BSZ * TDIM];
__device__ int g_cnt[BSZ];

// ---------------- helpers ----------------
__device__ __forceinline__ uint32_t smem_u32(const void* p) {
    uint32_t a;
    asm("{ .reg .u64 t; cvta.to.shared.u64 t, %1; cvt.u32.u64 %0, t; }" : "=r"(a) : "l"(p));
    return a;
}
__device__ __forceinline__ uint32_t sw128(uint32_t off) { return off ^ ((off >> 3) & 0x70); }

__device__ __forceinline__ void ldsm4(uint32_t* r, uint32_t addr) {
    asm volatile("ldmatrix.sync.aligned.m8n8.x4.shared.b16 {%0,%1,%2,%3}, [%4];"
        : "=r"(r[0]), "=r"(r[1]), "=r"(r[2]), "=r"(r[3]) : "r"(addr));
}
__device__ __forceinline__ void mma16816(float* c, const uint32_t* a, const uint32_t* b) {
    asm volatile("mma.sync.aligned.m16n8k16.row.col.f32.f16.f16.f32 "
        "{%0,%1,%2,%3}, {%4,%5,%6,%7}, {%8,%9}, {%0,%1,%2,%3};"
        : "+f"(c[0]), "+f"(c[1]), "+f"(c[2]), "+f"(c[3])
        : "r"(a[0]), "r"(a[1]), "r"(a[2]), "r"(a[3]), "r"(b[0]), "r"(b[1]));
}
// single-instruction cvt.rn.f16x2.f32 (same rn rounding as 2x __float2half)
__device__ __forceinline__ uint32_t pack2h(float v0, float v1) {
    __half2 t = __floats2half2_rn(v0, v1);
    return *(uint32_t*)&t;
}
__device__ __forceinline__ void cpasync16(uint32_t dst, const void* src) {
    asm volatile("cp.async.cg.shared.global [%0], [%1], 16;" :: "r"(dst), "l"(src));
}
#define CP_COMMIT() asm volatile("cp.async.commit_group;" ::: "memory")
#define CP_WAIT0()  asm volatile("cp.async.wait_group 0;" ::: "memory")
#define CP_WAIT1()  asm volatile("cp.async.wait_group 1;" ::: "memory")

// ---------------------------------------------------------------------------
__global__ __launch_bounds__(256)
void compact_kernel(const unsigned* __restrict__ mask, int* __restrict__ idx,
                    int* __restrict__ cnt)
{
    __shared__ int wsum[8];
    __shared__ int wexcl[8];
    const int b = blockIdx.x;
    const unsigned* mb = mask + (size_t)b * TDIM;
    int* ib = idx + (size_t)b * TDIM;
    const int tid  = threadIdx.x;
    const int lane = tid & 31, w = tid >> 5;
    unsigned v[8]; int c = 0;
#pragma unroll
    for (int i = 0; i < 8; ++i) { v[i] = mb[tid * 8 + i]; c += v[i] ? 1 : 0; }
    int inc = c;
#pragma unroll
    for (int off = 1; off < 32; off <<= 1) {
        int n = __shfl_up_sync(0xffffffffu, inc, off);
        if (lane >= off) inc += n;
    }
    if (lane == 31) wsum[w] = inc;
    __syncthreads();
    if (tid == 0) {
        int s = 0;
#pragma unroll
        for (int i = 0; i < 8; ++i) { wexcl[i] = s; s += wsum[i]; }
        cnt[b] = s;
    }
    __syncthreads();
    int p = wexcl[w] + inc - c;
#pragma unroll
    for (int i = 0; i < 8; ++i) if (v[i]) ib[p++] = tid * 8 + i;
}

// ---------------------------------------------------------------------------
// Fused prep: grid sections (split W | zero out | gather-transpose | tail).
// ---------------------------------------------------------------------------
#define PREP_ZERO0    2048
#define PREP_GATH0    2560
#define PREP_TAIL0    6656
#define PREP_BLOCKS   6672

__global__ __launch_bounds__(256)
void prep_kernel(const float* __restrict__ x, const unsigned* __restrict__ mask,
                 const int* __restrict__ idx, const int* __restrict__ cnt,
                 const float* __restrict__ w0, const float* __restrict__ w1,
                 const float* __restrict__ w2, const float* __restrict__ w3,
                 __half* __restrict__ wh, __half* __restrict__ xh,
                 float* __restrict__ out, int writeTail)
{
    const int bx = blockIdx.x;
    const int tid = threadIdx.x;

    if (bx < PREP_ZERO0) {
        const unsigned base = (unsigned)bx * 2048u + (unsigned)tid * 8u;
#pragma unroll
        for (int i = 0; i < 8; i += 4) {
            const unsigned idx4 = base + i;
            const int sel = idx4 >> 20;
            const float* w = (sel == 0) ? w0 : (sel == 1) ? w1 : (sel == 2) ? w2 : w3;
            float4 v = *(const float4*)(w + (idx4 & 0xFFFFFu));
            uint2 o;
            o.x = pack2h(v.x, v.y);
            o.y = pack2h(v.z, v.w);
            *(uint2*)(wh + idx4) = o;
        }
    } else if (bx < PREP_GATH0) {
        float4* p = (float4*)out;
        const unsigned base = (unsigned)(bx - PREP_ZERO0) * 2048u + (unsigned)tid * 8u;
#pragma unroll
        for (int i = 0; i < 8; ++i)
            p[base + i] = make_float4(0.f, 0.f, 0.f, 0.f);
    } else if (bx < PREP_TAIL0) {
        __shared__ float tile[32][33];
        __shared__ int tloc[32];
        const int g = bx - PREP_GATH0;
        const int b = g >> 11;
        const int rem = g & 2047;
        const int cy = rem >> 6;
        const int gx = rem & 63;
        const int n = cnt[b];
        const int i0 = gx * 32;
        if (i0 >= n) return;
        const int c0 = cy * 32;
        const float* s = x + (size_t)b * CDIM * TDIM;
        __half* ph = xh + (size_t)b * TDIM * CDIM;
        const int tx = tid & 31, ty = tid >> 5;
        if (ty == 0) tloc[tx] = (i0 + tx < n) ? idx[b * TDIM + i0 + tx] : -1;
        __syncthreads();
        const int t = tloc[tx];
#pragma unroll
        for (int i = 0; i < 4; ++i)
            tile[ty + i * 8][tx] = (t >= 0) ? s[(size_t)(c0 + ty + i * 8) * TDIM + t] : 0.f;
        __syncthreads();
#pragma unroll
        for (int i = 0; i < 4; ++i) {
            const int irow = i0 + ty + i * 8;
            if (irow < n)
                ph[(size_t)irow * CDIM + c0 + tx] = __float2half(tile[tx][ty + i * 8]);
        }
    } else {
        if (!writeTail) return;
        const int i = (bx - PREP_TAIL0) * 256 + tid;
        float* outTail = out + (size_t)BSZ * CDIM * TDIM;
        outTail[i] = mask[i] ? 1.0f : 0.0f;
    }
}

// ---------------------------------------------------------------------------
// fp16 GEMM, BK=64, 3-stage cp.async pipeline, direct epilogue.
// ---------------------------------------------------------------------------
extern __shared__ unsigned char dynsm[];

__global__ __launch_bounds__(256, 2)
void mma_gemm(const __half* __restrict__ Ah, const __half* __restrict__ Bh,
              const float* __restrict__ b0, const float* __restrict__ b1,
              const float* __restrict__ b2, float* __restrict__ Cout,
              __half* __restrict__ Qh, __half* __restrict__ Kh, __half* __restrict__ Vh,
              const int* __restrict__ cnt, const int* __restrict__ idx, int fusedQKV)
{
    __shared__ int sidx[128];

    const int b    = blockIdx.z;
    const int nlim = cnt[b];
    const int n0   = blockIdx.x * 128;
    if (n0 >= nlim) return;
    const int m0   = blockIdx.y * 128;
    const int tid  = threadIdx.x;
    const int wid  = tid >> 5;
    const int lane = tid & 31;
    const int wy   = wid & 1;
    const int wx   = wid >> 1;

    const uint32_t smu = smem_u32(dynsm);

    const int r   = tid & 127;
    const int isB = tid >> 7;
    const __half* Bhb = Bh + (size_t)b * TDIM * CDIM;
    const __half* srcP = isB ? (Bhb + (size_t)(n0 + r) * CDIM)
                             : (Ah + (size_t)(m0 + r) * CDIM);
    const uint32_t regOff = (uint32_t)isB * 16384u;
    uint32_t so[8];
#pragma unroll
    for (int i = 0; i < 8; ++i) so[i] = regOff + sw128((uint32_t)r * 128u + i * 16u);

    float acc[4][4][4];
#pragma unroll
    for (int i = 0; i < 4; ++i)
#pragma unroll
        for (int j = 0; j < 4; ++j)
#pragma unroll
            for (int c = 0; c < 4; ++c) acc[i][j][c] = 0.f;

    const uint32_t aRow = (uint32_t)(wy * 64 + (lane & 15));
    const uint32_t aCol = (uint32_t)((lane >> 4) << 4);
    const uint32_t bRow = (uint32_t)(wx * 32 + (lane & 7) + ((lane >> 4) << 3));
    const uint32_t bCol = (uint32_t)(((lane >> 3) & 1) << 4);

    {
#pragma unroll
        for (int i = 0; i < 8; ++i)
            cpasync16(smu + so[i], srcP + i * 8);
        CP_COMMIT();
#pragma unroll
        for (int i = 0; i < 8; ++i)
            cpasync16(smu + 32768u + so[i], srcP + 64 + i * 8);
        CP_COMMIT();
    }

    uint32_t stg = 0;
    uint32_t nst = 2 * 32768u;
    for (int kb = 0; kb < 16; ++kb) {
        if (kb < 15) { CP_WAIT1(); } else { CP_WAIT0(); }
        __syncthreads();
        if (kb + 2 < 16) {
            const int k2 = (kb + 2) * 64;
#pragma unroll
            for (int i = 0; i < 8; ++i)
                cpasync16(smu + nst + so[i], srcP + k2 + i * 8);
            CP_COMMIT();
        }

        const uint32_t smA_u = smu + stg;
        const uint32_t smB_u = smu + stg + 16384;
#pragma unroll
        for (int s = 0; s < 4; ++s) {
            const uint32_t ksA = s * 32;
            uint32_t afr[4][4], bfr[4][2];
#pragma unroll
            for (int mt = 0; mt < 4; ++mt)
                ldsm4(afr[mt], smA_u + sw128((aRow + mt * 16) * 128 + ksA + aCol));
#pragma unroll
            for (int np = 0; np < 2; ++np) {
                uint32_t rr[4];
                ldsm4(rr, smB_u + sw128((bRow + np * 16) * 128 + ksA + bCol));
                bfr[np * 2 + 0][0] = rr[0]; bfr[np * 2 + 0][1] = rr[1];
                bfr[np * 2 + 1][0] = rr[2]; bfr[np * 2 + 1][1] = rr[3];
            }
#pragma unroll
            for (int mt = 0; mt < 4; ++mt)
#pragma unroll
                for (int nt = 0; nt < 4; ++nt)
                    mma16816(acc[mt][nt], afr[mt], bfr[nt]);
        }
        stg = (stg == 2 * 32768u) ? 0u : stg + 32768u;
        nst = (nst == 2 * 32768u) ? 0u : nst + 32768u;
    }

    // ---- epilogue (direct stores) ----
    const int sector = m0 >> 10;
    const int mbase  = m0 & 1023;
    const float* bptr = fusedQKV ? (sector == 0 ? b0 : (sector == 1 ? b1 : b2)) : b0;

    if (!fusedQKV) {
        __syncthreads();
        if (tid < 128) sidx[tid] = (n0 + tid < nlim) ? idx[b * TDIM + n0 + tid] : -1;
        __syncthreads();
    }

    const int qrow = lane >> 2;
    const int qcol = (lane & 3) * 2;
#pragma unroll
    for (int mt = 0; mt < 4; ++mt) {
#pragma unroll
        for (int rh = 0; rh < 2; ++rh) {
            const int rloc = mbase + wy * 64 + mt * 16 + qrow + rh * 8;
            const float bi = bptr[rloc];
#pragma unroll
            for (int nt = 0; nt < 4; ++nt) {
                const int col = n0 + wx * 32 + nt * 8 + qcol;
                float v0 = acc[mt][nt][rh * 2 + 0] + bi;
                float v1 = acc[mt][nt][rh * 2 + 1] + bi;
                if (!fusedQKV) {
                    float* dst = Cout + (size_t)b * CDIM * TDIM + (size_t)rloc * TDIM;
                    const int t0 = sidx[col - n0 + 0];
                    const int t1 = sidx[col - n0 + 1];
                    if (t0 >= 0) dst[t0] = v0;
                    if (t1 >= 0) dst[t1] = v1;
                } else if (sector < 2) {
                    __half* oh = sector ? Kh : Qh;
                    const int hh = rloc >> 6, dd = rloc & 63;
                    const size_t a0 = ((size_t)(b * HN + hh) * TDIM + col) * DH + dd;
                    oh[a0]      = __float2half(v0);
                    oh[a0 + DH] = __float2half(v1);
                } else {
                    const size_t a0 = ((size_t)b * CDIM + rloc) * TDIM + col;
                    *(uint32_t*)&Vh[a0] = pack2h(v0, v1);
                }
            }
        }
    }
}

// ---------------------------------------------------------------------------
// fp16 flash attention: log2-domain softmax, branch-skipped rescale,
// double-buffered cp.async K/V, boundary checks peeled to the last tile.
// ---------------------------------------------------------------------------
__global__ __launch_bounds__(256, 2)
void attn_mma(const __half* __restrict__ Qh, const __half* __restrict__ Kh,
              const __half* __restrict__ Vh, const int* __restrict__ cnt,
              __half* __restrict__ Oh)
{
    __shared__ __align__(1024) unsigned char sm[49152];
    const int b = blockIdx.z, h = blockIdx.y;
    const int kend = cnt[b];
    const int q0 = blockIdx.x * 128;
    if (q0 >= kend) return;
    const int tid = threadIdx.x, wid = tid >> 5, lane = tid & 31;
    const uint32_t smu = smem_u32(sm);

    const __half* Qhb = Qh + ((size_t)(b * HN + h) * TDIM + q0) * DH;
#pragma unroll
    for (int it = 0; it < 4; ++it) {
        const int lin = it * 256 + tid;
        const int row = lin >> 3, qd = lin & 7;
        uint4 a = *(const uint4*)(Qhb + (size_t)row * DH + qd * 8);
        *(uint4*)(sm + 32768 + sw128((uint32_t)row * 128 + qd * 16)) = a;
    }
    __syncthreads();
    uint32_t qfh[4][4];
    {
        const uint32_t aRow = wid * 16 + (lane & 15);
        const uint32_t aColB = (lane >> 4) << 4;
#pragma unroll
        for (int kk = 0; kk < 4; ++kk)
            ldsm4(qfh[kk], smu + 32768 + sw128(aRow * 128 + kk * 32 + aColB));
    }

    float oacc[8][4];
#pragma unroll
    for (int i = 0; i < 8; ++i)
#pragma unroll
        for (int c = 0; c < 4; ++c) oacc[i][c] = 0.f;
    float mrow[2] = {-1e30f, -1e30f}, lrow[2] = {0.f, 0.f};
    const float K2 = 0.18033688f;   // 0.125 * log2(e)
    const uint32_t bRow  = (lane & 7) + ((lane >> 4) << 3);
    const uint32_t bColB = ((lane >> 3) & 1) << 4;
    const int jc = (lane & 3) * 2;

    const __half* Khb = Kh + ((size_t)(b * HN + h) * TDIM) * DH;
    const __half* Vhb = Vh + ((size_t)b * CDIM + h * DH) * TDIM;

    const int l0row = tid >> 3, lqd = tid & 7;
    const int l1row = 32 + l0row;
    const uint32_t soK0 = sw128((uint32_t)l0row * 128 + lqd * 16);
    const uint32_t soK1 = sw128((uint32_t)l1row * 128 + lqd * 16);

    {
        cpasync16(smu + soK0,        Khb + (size_t)l0row * DH + lqd * 8);
        cpasync16(smu + soK1,        Khb + (size_t)l1row * DH + lqd * 8);
        cpasync16(smu + 8192 + soK0, Vhb + (size_t)l0row * TDIM + lqd * 8);
        cpasync16(smu + 8192 + soK1, Vhb + (size_t)l1row * TDIM + lqd * 8);
        CP_COMMIT();
    }

    for (int k0 = 0; k0 < kend; k0 += 64) {
        const uint32_t stg = ((uint32_t)(k0 >> 6) & 1u) * 16384u;
        CP_WAIT0();
        __syncthreads();
        if (k0 + 64 < kend) {
            const uint32_t nst = stg ^ 16384u;
            const int kn = k0 + 64;
            cpasync16(smu + nst + soK0,        Khb + (size_t)(kn + l0row) * DH + lqd * 8);
            cpasync16(smu + nst + soK1,        Khb + (size_t)(kn + l1row) * DH + lqd * 8);
            cpasync16(smu + nst + 8192 + soK0, Vhb + (size_t)l0row * TDIM + kn + lqd * 8);
            cpasync16(smu + nst + 8192 + soK1, Vhb + (size_t)l1row * TDIM + kn + lqd * 8);
            CP_COMMIT();
        }

        float s[8][4];
#pragma unroll
        for (int i = 0; i < 8; ++i)
#pragma unroll
            for (int c = 0; c < 4; ++c) s[i][c] = 0.f;
#pragma unroll
        for (int kk = 0; kk < 4; ++kk) {
            uint32_t bfr[8][2];
#pragma unroll
            for (int np = 0; np < 4; ++np) {
                uint32_t rr[4];
                ldsm4(rr, smu + stg + sw128((np * 16 + bRow) * 128 + kk * 32 + bColB));
                bfr[np * 2 + 0][0] = rr[0]; bfr[np * 2 + 0][1] = rr[1];
                bfr[np * 2 + 1][0] = rr[2]; bfr[np * 2 + 1][1] = rr[3];
            }
#pragma unroll
            for (int nt = 0; nt < 8; ++nt) mma16816(s[nt], qfh[kk], bfr[nt]);
        }

        // ---- log2-domain online softmax; boundary checks only in edge tile ----
        const bool edge = (k0 + 64) > kend;
#pragma unroll
        for (int rh = 0; rh < 2; ++rh) {
            float mx = -1e30f;
            if (!edge) {
#pragma unroll
                for (int nt = 0; nt < 8; ++nt) {
                    float v0 = s[nt][rh * 2 + 0] * K2;
                    float v1 = s[nt][rh * 2 + 1] * K2;
                    s[nt][rh * 2 + 0] = v0; s[nt][rh * 2 + 1] = v1;
                    mx = fmaxf(mx, fmaxf(v0, v1));
                }
            } else {
#pragma unroll
                for (int nt = 0; nt < 8; ++nt) {
                    const int jg = k0 + nt * 8 + jc;
                    float v0 = (jg     < kend) ? s[nt][rh * 2 + 0] * K2 : -1e30f;
                    float v1 = (jg + 1 < kend) ? s[nt][rh * 2 + 1] * K2 : -1e30f;
                    s[nt][rh * 2 + 0] = v0; s[nt][rh * 2 + 1] = v1;
                    mx = fmaxf(mx, fmaxf(v0, v1));
                }
            }
            mx = fmaxf(mx, __shfl_xor_sync(0xffffffffu, mx, 1));
            mx = fmaxf(mx, __shfl_xor_sync(0xffffffffu, mx, 2));
            if (mx > mrow[rh]) {
                const float fac = exp2f(mrow[rh] - mx);
                mrow[rh] = mx;
                lrow[rh] *= fac;
#pragma unroll
                for (int nt = 0; nt < 8; ++nt) {
                    oacc[nt][rh * 2 + 0] *= fac;
                    oacc[nt][rh * 2 + 1] *= fac;
                }
            }
            const float m2 = mrow[rh];
            float sum = 0.f;
#pragma unroll
            for (int nt = 0; nt < 8; ++nt) {
                float p0 = exp2f(s[nt][rh * 2 + 0] - m2);
                float p1 = exp2f(s[nt][rh * 2 + 1] - m2);
                s[nt][rh * 2 + 0] = p0; s[nt][rh * 2 + 1] = p1;
                sum += p0 + p1;
            }
            sum += __shfl_xor_sync(0xffffffffu, sum, 1);
            sum += __shfl_xor_sync(0xffffffffu, sum, 2);
            lrow[rh] += sum;
        }

        uint32_t ph[4][4];
#pragma unroll
        for (int kk2 = 0; kk2 < 4; ++kk2) {
            const int t0 = 2 * kk2, t1 = 2 * kk2 + 1;
            ph[kk2][0] = pack2h(s[t0][0], s[t0][1]);
            ph[kk2][1] = pack2h(s[t0][2], s[t0][3]);
            ph[kk2][2] = pack2h(s[t1][0], s[t1][1]);
            ph[kk2][3] = pack2h(s[t1][2], s[t1][3]);
        }

#pragma unroll
        for (int kk2 = 0; kk2 < 4; ++kk2) {
            uint32_t vfr[8][2];
#pragma unroll
            for (int np = 0; np < 4; ++np) {
                uint32_t rr[4];
                ldsm4(rr, smu + stg + 8192 + sw128((np * 16 + bRow) * 128 + kk2 * 32 + bColB));
                vfr[np * 2 + 0][0] = rr[0]; vfr[np * 2 + 0][1] = rr[1];
                vfr[np * 2 + 1][0] = rr[2]; vfr[np * 2 + 1][1] = rr[3];
            }
#pragma unroll
            for (int nt = 0; nt < 8; ++nt) mma16816(oacc[nt], ph[kk2], vfr[nt]);
        }
    }

#pragma unroll
    for (int rh = 0; rh < 2; ++rh) {
        const int q = q0 + wid * 16 + (lane >> 2) + rh * 8;
        const float inv = (lrow[rh] > 0.f) ? (1.f / lrow[rh]) : 0.f;
        const size_t base = ((size_t)b * TDIM + q) * CDIM + h * DH;
#pragma unroll
        for (int nt = 0; nt < 8; ++nt) {
            const int d = nt * 8 + jc;
            *(uint32_t*)&Oh[base + d] =
                pack2h(oacc[nt][rh * 2 + 0] * inv, oacc[nt][rh * 2 + 1] * inv);
        }
    }
}

// ---------------------------------------------------------------------------
extern "C" void kernel_launch(void* const* d_in, const int* in_sizes, int n_in,
                              void* d_out, int out_size)
{
    const float*    x    = (const float*)d_in[0];
    const unsigned* mask = (const unsigned*)d_in[1];
    const float*    Wq   = (const float*)d_in[2];
    const float*    bq   = (const float*)d_in[3];
    const float*    Wk   = (const float*)d_in[4];
    const float*    bk   = (const float*)d_in[5];
    const float*    Wv   = (const float*)d_in[6];
    const float*    bv   = (const float*)d_in[7];
    const float*    Wp   = (const float*)d_in[8];
    const float*    bp   = (const float*)d_in[9];
    float* out = (float*)d_out;

    __half *wh, *xh, *ah, *qh, *kh, *vh;
    int *gidx, *gcnt;
    cudaGetSymbolAddress((void**)&wh,   g_Wh);
    cudaGetSymbolAddress((void**)&xh,   g_xTh);
    cudaGetSymbolAddress((void**)&ah,   g_aTh);
    cudaGetSymbolAddress((void**)&qh,   g_qh);
    cudaGetSymbolAddress((void**)&kh,   g_kh);
    cudaGetSymbolAddress((void**)&vh,   g_vh);
    cudaGetSymbolAddress((void**)&gidx, g_idx);
    cudaGetSymbolAddress((void**)&gcnt, g_cnt);

    static int smem_set = 0;
    if (!smem_set) {
        cudaFuncSetAttribute(mma_gemm, cudaFuncAttributeMaxDynamicSharedMemorySize, 98304);
        smem_set = 1;
    }

    const long long nout = (long long)BSZ * CDIM * TDIM;
    const int writeTail = (out_size - (int)nout) >= BSZ * TDIM ? 1 : 0;

    compact_kernel<<<BSZ, 256>>>(mask, gidx, gcnt);

    prep_kernel<<<PREP_BLOCKS, 256>>>(x, mask, gidx, gcnt,
                                      Wq, Wk, Wv, Wp, wh, xh, out, writeTail);

    const size_t WN = (size_t)CDIM * CDIM;
    dim3 gqkv(TDIM / 128, 24, BSZ);
    mma_gemm<<<gqkv, 256, 98304>>>(wh, xh, bq, bk, bv,
                                   nullptr, qh, kh, vh, gcnt, gidx, 1);

    dim3 ga(TDIM / 128, HN, BSZ);
    attn_mma<<<ga, 256>>>(qh, kh, vh, gcnt, ah);

    dim3 gp(TDIM / 128, CDIM / 128, BSZ);
    mma_gemm<<<gp, 256, 98304>>>(wh + 3 * WN, ah, bp, nullptr, nullptr,
                                 out, nullptr, nullptr, nullptr,
                                 gcnt, gidx, 0);
}